// round 15
// baseline (speedup 1.0000x reference)
#include <cuda_runtime.h>
#include <cuda_bf16.h>
#include <math.h>
#include <stdint.h>

// ---------------------------------------------------------------------------
// Problem constants: V=32000, E=512, H=512, L=2, B=8, S=512
// ---------------------------------------------------------------------------
#define SS   512
#define BB   8
#define EE   512
#define HH   512
#define D2   1024      // 2H
#define G4   2048      // 4H
#define VV   32000
#define NROW 4096      // B*S
#define X4   (2 * G4)  // combined projection width

// ---------------------------------------------------------------------------
// Device scratch (no cudaMalloc allowed)
// ---------------------------------------------------------------------------
__device__ float g_embx  [NROW * EE];
__device__ float g_xc    [NROW * X4];
__device__ float g_hf    [NROW * HH];
__device__ float g_hb    [NROW * HH];
__device__ float g_lay   [NROW * D2];
__device__ float g_query [NROW * D2];
__device__ float g_scores[BB * SS * SS];
__device__ float g_ctx   [NROW * D2];
__device__ float g_pre   [NROW * D2];
__device__ float g_hpre  [NROW * HH];
__device__ float g_hcur  [2 * 2 * BB * HH];
__device__ float g_bcat  [X4];
__device__ int   g_len   [BB];
__device__ unsigned g_barcnt2[2];

// bf16 split operand buffers
__device__ __nv_bfloat16 g_ahi  [NROW * D2];
__device__ __nv_bfloat16 g_alo  [NROW * D2];
__device__ __nv_bfloat16 g_bhi  [NROW * D2];
__device__ __nv_bfloat16 g_blo  [NROW * D2];
__device__ __nv_bfloat16 g_ehi  [NROW * D2];
__device__ __nv_bfloat16 g_elo  [NROW * D2];
__device__ __nv_bfloat16 g_hhi  [NROW * HH];
__device__ __nv_bfloat16 g_hlo  [NROW * HH];
__device__ __nv_bfloat16 g_wpthi[(long)VV * HH];
__device__ __nv_bfloat16 g_wptlo[(long)VV * HH];

__device__ __forceinline__ float sigm(float x) { return 1.f / (1.f + expf(-x)); }

__device__ __forceinline__ uint32_t smem_u32(const void* p) {
    uint32_t a;
    asm("{ .reg .u64 t; cvta.to.shared.u64 t, %1; cvt.u32.u64 %0, t; }"
        : "=r"(a) : "l"(p));
    return a;
}

__device__ __forceinline__ void mma_bf16(float* c, const uint32_t* a,
                                         const uint32_t* b) {
    asm volatile(
        "mma.sync.aligned.m16n8k16.row.col.f32.bf16.bf16.f32 "
        "{%0,%1,%2,%3}, {%4,%5,%6,%7}, {%8,%9}, {%0,%1,%2,%3};"
        : "+f"(c[0]), "+f"(c[1]), "+f"(c[2]), "+f"(c[3])
        : "r"(a[0]), "r"(a[1]), "r"(a[2]), "r"(a[3]), "r"(b[0]), "r"(b[1]));
}

__device__ __forceinline__ void ldsm_x4(uint32_t& r0, uint32_t& r1,
                                        uint32_t& r2, uint32_t& r3,
                                        uint32_t addr) {
    asm volatile("ldmatrix.sync.aligned.m8n8.x4.shared.b16 {%0,%1,%2,%3}, [%4];"
                 : "=r"(r0), "=r"(r1), "=r"(r2), "=r"(r3) : "r"(addr));
}

#define CP_ASYNC16(dst, src) \
    asm volatile("cp.async.cg.shared.global [%0], [%1], 16;" \
                 :: "r"(dst), "l"(src) : "memory")
#define CP_COMMIT() asm volatile("cp.async.commit_group;" ::: "memory")
#define CP_WAIT0()  asm volatile("cp.async.wait_group 0;" ::: "memory")
#define CP_WAIT1()  asm volatile("cp.async.wait_group 1;" ::: "memory")
#define CP_WAIT2()  asm volatile("cp.async.wait_group 2;" ::: "memory")

// ---------------------------------------------------------------------------
// lengths per batch
// ---------------------------------------------------------------------------
__global__ void len_kernel(const int* __restrict__ x, int* __restrict__ len) {
    __shared__ int red[512];
    int b = blockIdx.x, tid = threadIdx.x;
    red[tid] = (x[b * SS + tid] != 0) ? 1 : 0;
    __syncthreads();
    for (int s = 256; s > 0; s >>= 1) {
        if (tid < s) red[tid] += red[tid + s];
        __syncthreads();
    }
    if (tid == 0) len[b] = red[0];
}

// ---------------------------------------------------------------------------
// embedding gather
// ---------------------------------------------------------------------------
__global__ void embed_kernel(const int* __restrict__ x, const float* __restrict__ emb,
                             float* __restrict__ out) {
    int r = blockIdx.x;
    long tok = (long)x[r];
    float4 v = ((const float4*)(emb + tok * EE))[threadIdx.x];
    ((float4*)(out + (long)r * EE))[threadIdx.x] = v;
}

// ---------------------------------------------------------------------------
// split fp32 -> bf16 hi/lo
// ---------------------------------------------------------------------------
__global__ void split_f32(const float* __restrict__ in,
                          __nv_bfloat16* __restrict__ hi,
                          __nv_bfloat16* __restrict__ lo, int n4) {
    int i = blockIdx.x * blockDim.x + threadIdx.x;
    if (i >= n4) return;
    float4 v = ((const float4*)in)[i];
    __nv_bfloat16 h0 = __float2bfloat16(v.x);
    __nv_bfloat16 h1 = __float2bfloat16(v.y);
    __nv_bfloat16 h2 = __float2bfloat16(v.z);
    __nv_bfloat16 h3 = __float2bfloat16(v.w);
    __nv_bfloat162 ph0 = {h0, h1}, ph1 = {h2, h3};
    __nv_bfloat162 pl0 = {__float2bfloat16(v.x - __bfloat162float(h0)),
                          __float2bfloat16(v.y - __bfloat162float(h1))};
    __nv_bfloat162 pl1 = {__float2bfloat16(v.z - __bfloat162float(h2)),
                          __float2bfloat16(v.w - __bfloat162float(h3))};
    ((__nv_bfloat162*)hi)[i * 2]     = ph0;
    ((__nv_bfloat162*)hi)[i * 2 + 1] = ph1;
    ((__nv_bfloat162*)lo)[i * 2]     = pl0;
    ((__nv_bfloat162*)lo)[i * 2 + 1] = pl1;
}

// ---------------------------------------------------------------------------
// Transpose + split: W[K, N] (row stride ldw) -> T{hi,lo}[N][K]
// ---------------------------------------------------------------------------
__global__ void wt_split(const float* __restrict__ W, int ldw, int K,
                         __nv_bfloat16* __restrict__ Thi,
                         __nv_bfloat16* __restrict__ Tlo,
                         long strW, long strT) {
    __shared__ float tile[32][33];
    W   += (long)blockIdx.z * strW;
    Thi += (long)blockIdx.z * strT;
    Tlo += (long)blockIdx.z * strT;
    int n0 = blockIdx.x * 32, k0 = blockIdx.y * 32;
    int tx = threadIdx.x, ty = threadIdx.y;
#pragma unroll
    for (int i = 0; i < 4; i++)
        tile[ty + i * 8][tx] = W[(long)(k0 + ty + i * 8) * ldw + n0 + tx];
    __syncthreads();
#pragma unroll
    for (int i = 0; i < 4; i++) {
        int n = n0 + ty + i * 8, k = k0 + tx;
        float v = tile[tx][ty + i * 8];
        __nv_bfloat16 hi = __float2bfloat16(v);
        float lo = v - __bfloat162float(hi);
        Thi[(long)n * K + k] = hi;
        Tlo[(long)n * K + k] = __float2bfloat16(lo);
    }
}

// ---------------------------------------------------------------------------
// Generic split-bf16 mma.sync GEMM, cp.async 3-stage pipelined.
// CTA tile 128x128, K-slab 32, 8 warps (4m x 2n), warp tile 32x64.
// ---------------------------------------------------------------------------
#define WROW 40
#define HS_ARR   (128 * WROW)
#define HS_PERBUF (4 * HS_ARR)
#define HGEMM_SMEM (3 * HS_PERBUF * 2)   // 122880 B

__global__ __launch_bounds__(256) void hgemm(
    const __nv_bfloat16* __restrict__ Ahi, const __nv_bfloat16* __restrict__ Alo,
    const __nv_bfloat16* __restrict__ Bhi, const __nv_bfloat16* __restrict__ Blo,
    const float* __restrict__ bias, float* __restrict__ C,
    int N, int K, int ldc, float scale, int accum,
    long strA, long strB, long strC)
{
    extern __shared__ __nv_bfloat16 hs[];
    Ahi += (long)blockIdx.z * strA;  Alo += (long)blockIdx.z * strA;
    Bhi += (long)blockIdx.z * strB;  Blo += (long)blockIdx.z * strB;
    C   += (long)blockIdx.z * strC;

    const int tid  = threadIdx.x;
    const int warp = tid >> 5, lane = tid & 31;
    const int wm = (warp & 3) * 32;
    const int wn = (warp >> 2) * 64;
    const int m0 = blockIdx.x * 128, n0 = blockIdx.y * 128;
    const int nk = K >> 5;

    const int lr = tid >> 1;
    const int lu = (tid & 1) * 16;
    const __nv_bfloat16* gAhi = Ahi + (long)(m0 + lr) * K + lu;
    const __nv_bfloat16* gAlo = Alo + (long)(m0 + lr) * K + lu;
    const __nv_bfloat16* gBhi = Bhi + (long)(n0 + lr) * K + lu;
    const __nv_bfloat16* gBlo = Blo + (long)(n0 + lr) * K + lu;
    const uint32_t sbase = smem_u32(hs);
    const uint32_t so = (lr * WROW + lu) * 2;

    const int a_r = (lane & 15);
    const int a_c = (lane >> 4) << 3;
    const int b_r = ((lane >> 4) << 3) + (lane & 7);
    const int b_c = ((lane >> 3) & 1) << 3;

    float acc[16][4];
#pragma unroll
    for (int i = 0; i < 16; i++)
#pragma unroll
        for (int j = 0; j < 4; j++) acc[i][j] = 0.f;

#define ISSUE(kb, buf)                                                       \
    do {                                                                     \
        const int _ko = (kb) * 32;                                           \
        uint32_t _d = sbase + (uint32_t)(buf) * (HS_PERBUF * 2) + so;        \
        CP_ASYNC16(_d,                  gAhi + _ko);                         \
        CP_ASYNC16(_d + 16,             gAhi + _ko + 8);                     \
        CP_ASYNC16(_d + HS_ARR * 2,     gAlo + _ko);                         \
        CP_ASYNC16(_d + HS_ARR * 2 + 16, gAlo + _ko + 8);                    \
        CP_ASYNC16(_d + HS_ARR * 4,     gBhi + _ko);                         \
        CP_ASYNC16(_d + HS_ARR * 4 + 16, gBhi + _ko + 8);                    \
        CP_ASYNC16(_d + HS_ARR * 6,     gBlo + _ko);                         \
        CP_ASYNC16(_d + HS_ARR * 6 + 16, gBlo + _ko + 8);                    \
    } while (0)

    ISSUE(0, 0);
    CP_COMMIT();
    if (nk > 1) { ISSUE(1, 1); CP_COMMIT(); }

    int buf = 0;
    for (int kb = 0; kb < nk; kb++) {
        if (kb + 2 < nk) {
            int nbuf = (buf + 2) % 3;
            ISSUE(kb + 2, nbuf);
            CP_COMMIT();
            CP_WAIT2();
        } else if (kb + 1 < nk) {
            CP_WAIT1();
        } else {
            CP_WAIT0();
        }
        __syncthreads();

        const uint32_t bufb = sbase + (uint32_t)buf * (HS_PERBUF * 2);
#pragma unroll
        for (int kh = 0; kh < 32; kh += 16) {
            uint32_t ah[2][4], al[2][4];
#pragma unroll
            for (int mt = 0; mt < 2; mt++) {
                uint32_t off = bufb + ((wm + mt * 16 + a_r) * WROW + kh + a_c) * 2;
                ldsm_x4(ah[mt][0], ah[mt][1], ah[mt][2], ah[mt][3], off);
                ldsm_x4(al[mt][0], al[mt][1], al[mt][2], al[mt][3],
                        off + HS_ARR * 2);
            }
            uint32_t bh[8][2], bl[8][2];
#pragma unroll
            for (int p = 0; p < 4; p++) {
                uint32_t off = bufb + HS_ARR * 4 +
                               ((wn + p * 16 + b_r) * WROW + kh + b_c) * 2;
                ldsm_x4(bh[p * 2][0], bh[p * 2][1], bh[p * 2 + 1][0],
                        bh[p * 2 + 1][1], off);
                ldsm_x4(bl[p * 2][0], bl[p * 2][1], bl[p * 2 + 1][0],
                        bl[p * 2 + 1][1], off + HS_ARR * 2);
            }
#pragma unroll
            for (int mt = 0; mt < 2; mt++)
#pragma unroll
                for (int nt = 0; nt < 8; nt++) {
                    float* c = acc[mt * 8 + nt];
                    mma_bf16(c, ah[mt], bh[nt]);
                    mma_bf16(c, ah[mt], bl[nt]);
                    mma_bf16(c, al[mt], bh[nt]);
                }
        }
        __syncthreads();
        buf = (buf + 1) % 3;
    }
#undef ISSUE

    const int g  = lane >> 2;
    const int c2 = (lane & 3) * 2;
#pragma unroll
    for (int nt = 0; nt < 8; nt++) {
        const int col = n0 + wn + nt * 8 + c2;
        float b0 = 0.f, b1 = 0.f;
        if (bias) { b0 = bias[col]; b1 = bias[col + 1]; }
#pragma unroll
        for (int mt = 0; mt < 2; mt++) {
            const float* c = acc[mt * 8 + nt];
            const int r0 = m0 + wm + mt * 16 + g;
            long o0 = (long)r0 * ldc + col;
            long o1 = (long)(r0 + 8) * ldc + col;
            float2 v0 = make_float2(c[0] * scale + b0, c[1] * scale + b1);
            float2 v1 = make_float2(c[2] * scale + b0, c[3] * scale + b1);
            if (accum) {
                float2 e0 = *(const float2*)(C + o0);
                float2 e1 = *(const float2*)(C + o1);
                v0.x += e0.x; v0.y += e0.y; v1.x += e1.x; v1.y += e1.y;
            }
            *(float2*)(C + o0) = v0;
            *(float2*)(C + o1) = v1;
        }
    }
}

// ---------------------------------------------------------------------------
// Masked softmax per (b, q) row
// ---------------------------------------------------------------------------
__global__ void softmax_kernel(float* __restrict__ sc, const int* __restrict__ len) {
    const int q = blockIdx.x, b = blockIdx.y;
    float* row = sc + ((long)b * SS + q) * SS;
    const int L = len[b];
    const int t = threadIdx.x;
    __shared__ float red[256];
    if (q >= L) {
        for (int i = t; i < SS; i += 256) row[i] = 0.f;
        return;
    }
    float m = -3.402823466e38f;
    for (int i = t; i < L; i += 256) m = fmaxf(m, row[i]);
    red[t] = m; __syncthreads();
    for (int s = 128; s > 0; s >>= 1) {
        if (t < s) red[t] = fmaxf(red[t], red[t + s]);
        __syncthreads();
    }
    m = red[0]; __syncthreads();
    float sum = 0.f;
    for (int i = t; i < L; i += 256) sum += expf(row[i] - m);
    red[t] = sum; __syncthreads();
    for (int s = 128; s > 0; s >>= 1) {
        if (t < s) red[t] += red[t + s];
        __syncthreads();
    }
    float inv = 1.f / red[0];
    for (int i = t; i < SS; i += 256)
        row[i] = (i < L) ? expf(row[i] - m) * inv : 0.f;
}

// ---------------------------------------------------------------------------
// Build layer input + fused bf16 hi/lo split
// ---------------------------------------------------------------------------
__global__ void build_lay(const float* __restrict__ hf, const float* __restrict__ hb,
                          const int* __restrict__ len, float* __restrict__ lay,
                          __nv_bfloat16* __restrict__ shi,
                          __nv_bfloat16* __restrict__ slo) {
    int r = blockIdx.x;
    int b = r >> 9, tt = r & 511;
    int active = tt < len[b];
    int t = threadIdx.x;
    for (int i = t; i < D2; i += 256) {
        float v = 0.f;
        if (active) v = (i < HH) ? hf[(long)r * HH + i] : hb[(long)r * HH + i - HH];
        lay[(long)r * D2 + i] = v;
        __nv_bfloat16 hi = __float2bfloat16(v);
        shi[(long)r * D2 + i] = hi;
        slo[(long)r * D2 + i] = __float2bfloat16(v - __bfloat162float(hi));
    }
}

// ---------------------------------------------------------------------------
// refined = LN(encoded + tanh(pre)) masked; emits bf16 hi/lo only
// ---------------------------------------------------------------------------
__global__ void refine_ln(const float* __restrict__ enc, const float* __restrict__ pre,
                          const float* __restrict__ g, const float* __restrict__ bta,
                          const int* __restrict__ len,
                          __nv_bfloat16* __restrict__ shi,
                          __nv_bfloat16* __restrict__ slo) {
    int r = blockIdx.x;
    int b = r >> 9, tt = r & 511;
    int t = threadIdx.x;
    __shared__ float r1[256], r2[256];
    float v[4];
    float s = 0.f, s2 = 0.f;
#pragma unroll
    for (int i = 0; i < 4; i++) {
        int idx = t + i * 256;
        float xx = enc[(long)r * D2 + idx] + tanhf(pre[(long)r * D2 + idx]);
        v[i] = xx; s += xx; s2 += xx * xx;
    }
    r1[t] = s; r2[t] = s2; __syncthreads();
    for (int st = 128; st > 0; st >>= 1) {
        if (t < st) { r1[t] += r1[t + st]; r2[t] += r2[t + st]; }
        __syncthreads();
    }
    float mean = r1[0] * (1.f / 1024.f);
    float var = r2[0] * (1.f / 1024.f) - mean * mean;
    float inv = rsqrtf(var + 1e-5f);
    int active = tt < len[b];
#pragma unroll
    for (int i = 0; i < 4; i++) {
        int idx = t + i * 256;
        float o = (v[i] - mean) * inv * g[idx] + bta[idx];
        o = active ? o : 0.f;
        __nv_bfloat16 hi = __float2bfloat16(o);
        shi[(long)r * D2 + idx] = hi;
        slo[(long)r * D2 + idx] = __float2bfloat16(o - __bfloat162float(hi));
    }
}

// ---------------------------------------------------------------------------
// head = LN(gelu_exact(hpre)) -> emit bf16 hi/lo split
// ---------------------------------------------------------------------------
__global__ void head_ln(const float* __restrict__ hpre, const float* __restrict__ g,
                        const float* __restrict__ bta,
                        __nv_bfloat16* __restrict__ hhi,
                        __nv_bfloat16* __restrict__ hlo) {
    int r = blockIdx.x;
    int t = threadIdx.x;
    __shared__ float r1[256], r2[256];
    float v[2];
    float s = 0.f, s2 = 0.f;
#pragma unroll
    for (int i = 0; i < 2; i++) {
        int idx = t + i * 256;
        float xx = hpre[(long)r * HH + idx];
        float ge = 0.5f * xx * (1.f + erff(xx * 0.70710678118654752f));
        v[i] = ge; s += ge; s2 += ge * ge;
    }
    r1[t] = s; r2[t] = s2; __syncthreads();
    for (int st = 128; st > 0; st >>= 1) {
        if (t < st) { r1[t] += r1[t + st]; r2[t] += r2[t + st]; }
        __syncthreads();
    }
    float mean = r1[0] * (1.f / 512.f);
    float var = r2[0] * (1.f / 512.f) - mean * mean;
    float inv = rsqrtf(var + 1e-5f);
#pragma unroll
    for (int i = 0; i < 2; i++) {
        int idx = t + i * 256;
        float o = (v[i] - mean) * inv * g[idx] + bta[idx];
        __nv_bfloat16 hi = __float2bfloat16(o);
        float lo = o - __bfloat162float(hi);
        hhi[(long)r * HH + idx] = hi;
        hlo[(long)r * HH + idx] = __float2bfloat16(lo);
    }
}

// ---------------------------------------------------------------------------
// Reset grid barrier counters
// ---------------------------------------------------------------------------
__global__ void reset_bar() { g_barcnt2[0] = 0u; g_barcnt2[1] = 0u; }

// ---------------------------------------------------------------------------
// Persistent BiLSTM scan — tensor-core GEMV (unchanged; xp row stride X4)
// ---------------------------------------------------------------------------
#define LROW 520
#define LS_W   (16 * LROW)
#define LSTM_SMEM (4 * LS_W * 2 + 1024 * 4 + 128 * 4 + 32 * 4)

__global__ __launch_bounds__(256, 2) void lstm_scan(
    const float* __restrict__ xc,
    const float* __restrict__ Wrf, const float* __restrict__ Wrb,
    const float* __restrict__ h0f, const float* __restrict__ c0f,
    const float* __restrict__ h0b, const float* __restrict__ c0b,
    float* __restrict__ houtf, float* __restrict__ houtb,
    float* __restrict__ hcur, const int* __restrict__ len)
{
    extern __shared__ char smraw[];
    __nv_bfloat16* sWhi = (__nv_bfloat16*)smraw;
    __nv_bfloat16* sWlo = sWhi + LS_W;
    __nv_bfloat16* sAhi = sWlo + LS_W;
    __nv_bfloat16* sAlo = sAhi + LS_W;
    float* part  = (float*)(sAlo + LS_W);
    float* gates = part + 1024;
    float* cst   = gates + 128;

    const int tid  = threadIdx.x;
    const int warp = tid >> 5, lane = tid & 31;
    const int dir = blockIdx.x >> 7;
    const int kb  = blockIdx.x & 127;
    const int j0  = kb * 4;
    const float* Wr = dir ? Wrb : Wrf;
    const float* xp = xc + dir * G4;
    const float* h0 = dir ? h0b : h0f;
    const float* c0 = dir ? c0b : c0f;
    float* hout  = dir ? houtb : houtf;
    float* hbase = hcur + dir * (2 * BB * HH);
    volatile unsigned* barp = &g_barcnt2[dir];

    {
        int col = tid & 15;
        int gcol = (col >> 2) * 512 + j0 + (col & 3);
        for (int k = tid >> 4; k < 512; k += 16) {
            float v = Wr[(long)k * G4 + gcol];
            __nv_bfloat16 hi = __float2bfloat16(v);
            sWhi[col * LROW + k] = hi;
            sWlo[col * LROW + k] = __float2bfloat16(v - __bfloat162float(hi));
        }
    }
    for (int f = tid; f < 8 * LROW; f += 256) {
        sAhi[8 * LROW + f] = __float2bfloat16(0.f);
        sAlo[8 * LROW + f] = __float2bfloat16(0.f);
    }
    if (tid < 32) {
        int u = tid >> 3, b = tid & 7;
        cst[u * 8 + b] = c0[j0 + u];
        __stcg(&hbase[(j0 + u) * 8 + b], h0[j0 + u]);
    }

    const uint32_t sAhiB = smem_u32(sAhi), sAloB = smem_u32(sAlo);
    const uint32_t sWhiB = smem_u32(sWhi), sWloB = smem_u32(sWlo);
    const int kbase = warp * 64;
    const uint32_t aoff = ((lane & 15) * LROW + kbase + ((lane >> 4) << 3)) * 2;
    const uint32_t boff = ((((lane >> 4) << 3) + (lane & 7)) * LROW + kbase +
                          (((lane >> 3) & 1) << 3)) * 2;

    unsigned phase = 1;
#define GRIDBAR()                                                         \
    do {                                                                  \
        __syncthreads();                                                  \
        if (tid == 0) {                                                   \
            __threadfence();                                              \
            atomicAdd((unsigned*)barp, 1u);                               \
            unsigned tgt = 128u * phase;                                  \
            while (*barp < tgt) {}                                        \
        }                                                                 \
        __syncthreads();                                                  \
        phase++;                                                          \
    } while (0)

    GRIDBAR();

    for (int s = 0; s < SS; s++) {
        const float* hrd = hbase + (s & 1) * (BB * HH);
        float* hwr = hbase + ((s + 1) & 1) * (BB * HH);
        const int t_real = dir ? (SS - 1 - s) : s;

        float xpv = 0.f;
        if (tid < 128) {
            int col = tid >> 3, b = tid & 7;
            xpv = __ldg(&xp[((long)(b * SS + t_real)) * X4 +
                            (col >> 2) * 512 + j0 + (col & 3)]);
        }
        float hpv = 0.f;
        if (tid < 32)
            hpv = __ldcg(&hrd[(j0 + (tid >> 3)) * 8 + (tid & 7)]);

        {
            int b = tid & 7, kp = tid >> 3;
#pragma unroll
            for (int i = 0; i < 8; i++) {
                int k = (kp + 32 * i) * 2;
                float v0 = __ldcg(hrd + k * 8 + b);
                float v1 = __ldcg(hrd + (k + 1) * 8 + b);
                __nv_bfloat16 hh0 = __float2bfloat16(v0);
                __nv_bfloat16 hh1 = __float2bfloat16(v1);
                __nv_bfloat162 ph = {hh0, hh1};
                __nv_bfloat162 pl = {__float2bfloat16(v0 - __bfloat162float(hh0)),
                                     __float2bfloat16(v1 - __bfloat162float(hh1))};
                *(__nv_bfloat162*)&sAhi[b * LROW + k] = ph;
                *(__nv_bfloat162*)&sAlo[b * LROW + k] = pl;
            }
        }
        __syncthreads();

        float acA[2][4], acB[2][4];
#pragma unroll
        for (int nt = 0; nt < 2; nt++)
#pragma unroll
            for (int j = 0; j < 4; j++) { acA[nt][j] = 0.f; acB[nt][j] = 0.f; }
#pragma unroll
        for (int kk = 0; kk < 4; kk++) {
            uint32_t ah[4], al[4], bh4[4], bl4[4];
            ldsm_x4(ah[0], ah[1], ah[2], ah[3], sAhiB + aoff + kk * 32);
            ldsm_x4(al[0], al[1], al[2], al[3], sAloB + aoff + kk * 32);
            ldsm_x4(bh4[0], bh4[1], bh4[2], bh4[3], sWhiB + boff + kk * 32);
            ldsm_x4(bl4[0], bl4[1], bl4[2], bl4[3], sWloB + boff + kk * 32);
            float (*ac)[4] = (kk & 1) ? acB : acA;
            uint32_t bh0[2] = {bh4[0], bh4[1]}, bh1[2] = {bh4[2], bh4[3]};
            uint32_t bl0[2] = {bl4[0], bl4[1]}, bl1[2] = {bl4[2], bl4[3]};
            mma_bf16(ac[0], ah, bh0);
            mma_bf16(ac[0], ah, bl0);
            mma_bf16(ac[0], al, bh0);
            mma_bf16(ac[1], ah, bh1);
            mma_bf16(ac[1], ah, bl1);
            mma_bf16(ac[1], al, bh1);
        }
        {
            int g = lane >> 2, c2 = (lane & 3) * 2;
#pragma unroll
            for (int nt = 0; nt < 2; nt++) {
                part[warp * 128 + (nt * 8 + c2) * 8 + g]     = acA[nt][0] + acB[nt][0];
                part[warp * 128 + (nt * 8 + c2 + 1) * 8 + g] = acA[nt][1] + acB[nt][1];
            }
        }
        __syncthreads();

        if (tid < 128) {
            float ssum = xpv;
#pragma unroll
            for (int w = 0; w < 8; w++) ssum += part[w * 128 + tid];
            gates[tid] = ssum;
        }
        __syncthreads();

        if (tid < 32) {
            int u = tid >> 3, b = tid & 7;
            float ig = gates[(u) * 8 + b];
            float fg = gates[(4 + u) * 8 + b];
            float og = gates[(8 + u) * 8 + b];
            float gg = gates[(12 + u) * 8 + b];
            float cp = cst[u * 8 + b];
            float cn = sigm(fg) * cp + sigm(ig) * tanhf(gg);
            float hn = sigm(og) * tanhf(cn);
            int active = t_real < len[b];
            float h = active ? hn : hpv;
            float c = active ? cn : cp;
            cst[u * 8 + b] = c;
            __stcg(&hwr[(j0 + u) * 8 + b], h);
            hout[((long)(b * SS + t_real)) * HH + j0 + u] = h;
        }
        GRIDBAR();
    }
#undef GRIDBAR
}

// ---------------------------------------------------------------------------
// Host driver
// ---------------------------------------------------------------------------
extern "C" void kernel_launch(void* const* d_in, const int* in_sizes, int n_in,
                              void* d_out, int out_size) {
    const int*   x    = (const int*)  d_in[0];
    const float* emb  = (const float*)d_in[1];
    const float* Wf0  = (const float*)d_in[2];
    const float* bf0  = (const float*)d_in[3];
    const float* Wb0  = (const float*)d_in[4];
    const float* bb0  = (const float*)d_in[5];
    const float* Wf1  = (const float*)d_in[6];
    const float* bf1  = (const float*)d_in[7];
    const float* Wb1  = (const float*)d_in[8];
    const float* bb1  = (const float*)d_in[9];
    const float* h0f  = (const float*)d_in[10];
    const float* c0f  = (const float*)d_in[11];
    const float* h0b  = (const float*)d_in[12];
    const float* c0b  = (const float*)d_in[13];
    const float* Wq   = (const float*)d_in[14];
    const float* bq   = (const float*)d_in[15];
    const float* Wao  = (const float*)d_in[16];
    const float* bao  = (const float*)d_in[17];
    const float* ln1g = (const float*)d_in[18];
    const float* ln1b = (const float*)d_in[19];
    const float* Wh   = (const float*)d_in[20];
    const float* bh   = (const float*)d_in[21];
    const float* ln2g = (const float*)d_in[22];
    const float* ln2b = (const float*)d_in[23];
    const float* Wp   = (const float*)d_in[24];
    const float* ob   = (const float*)d_in[25];
    float* out = (float*)d_out;

    float *embx, *xc, *hf, *hb, *lay, *query, *scores, *ctx, *pre,
          *hpre, *hcur, *bcat;
    __nv_bfloat16 *ahi, *alo, *bhi, *blo, *ehi, *elo, *hhi, *hlo, *wpthi, *wptlo;
    int* len;
    cudaGetSymbolAddress((void**)&embx,   g_embx);
    cudaGetSymbolAddress((void**)&xc,     g_xc);
    cudaGetSymbolAddress((void**)&hf,     g_hf);
    cudaGetSymbolAddress((void**)&hb,     g_hb);
    cudaGetSymbolAddress((void**)&lay,    g_lay);
    cudaGetSymbolAddress((void**)&query,  g_query);
    cudaGetSymbolAddress((void**)&scores, g_scores);
    cudaGetSymbolAddress((void**)&ctx,    g_ctx);
    cudaGetSymbolAddress((void**)&pre,    g_pre);
    cudaGetSymbolAddress((void**)&hpre,   g_hpre);
    cudaGetSymbolAddress((void**)&hcur,   g_hcur);
    cudaGetSymbolAddress((void**)&bcat,   g_bcat);
    cudaGetSymbolAddress((void**)&len,    g_len);
    cudaGetSymbolAddress((void**)&ahi,    g_ahi);
    cudaGetSymbolAddress((void**)&alo,    g_alo);
    cudaGetSymbolAddress((void**)&bhi,    g_bhi);
    cudaGetSymbolAddress((void**)&blo,    g_blo);
    cudaGetSymbolAddress((void**)&ehi,    g_ehi);
    cudaGetSymbolAddress((void**)&elo,    g_elo);
    cudaGetSymbolAddress((void**)&hhi,    g_hhi);
    cudaGetSymbolAddress((void**)&hlo,    g_hlo);
    cudaGetSymbolAddress((void**)&wpthi,  g_wpthi);
    cudaGetSymbolAddress((void**)&wptlo,  g_wptlo);

    cudaFuncSetAttribute(lstm_scan, cudaFuncAttributeMaxDynamicSharedMemorySize,
                         LSTM_SMEM);
    cudaFuncSetAttribute(hgemm, cudaFuncAttributeMaxDynamicSharedMemorySize,
                         HGEMM_SMEM);

    len_kernel<<<BB, 512>>>(x, len);
    embed_kernel<<<NROW, 128>>>(x, emb, embx);
    wt_split<<<dim3(VV / 32, HH / 32), dim3(32, 8)>>>(Wp, VV, HH, wpthi, wptlo, 0, 0);

    // ---- layer 0: combined projection (Wf0 | Wb0), N = 4096 ----
    split_f32<<<(NROW * EE / 4 + 255) / 256, 256>>>(embx, ahi, alo, NROW * EE / 4);
    wt_split<<<dim3(G4 / 32, EE / 32), dim3(32, 8)>>>(Wf0, G4, EE, bhi, blo, 0, 0);
    wt_split<<<dim3(G4 / 32, EE / 32), dim3(32, 8)>>>(Wb0, G4, EE,
        bhi + (long)G4 * EE, blo + (long)G4 * EE, 0, 0);
    cudaMemcpyAsync(bcat, bf0, G4 * sizeof(float), cudaMemcpyDeviceToDevice);
    cudaMemcpyAsync(bcat + G4, bb0, G4 * sizeof(float), cudaMemcpyDeviceToDevice);
    hgemm<<<dim3(NROW / 128, X4 / 128), 256, HGEMM_SMEM>>>(
        ahi, alo, bhi, blo, bcat, xc, X4, EE, X4, 1.f, 0, 0, 0, 0);

    reset_bar<<<1, 1>>>();
    lstm_scan<<<256, 256, LSTM_SMEM>>>(xc,
                                       Wf0 + (long)EE * G4, Wb0 + (long)EE * G4,
                                       h0f, c0f, h0b, c0b, hf, hb, hcur, len);
    build_lay<<<NROW, 256>>>(hf, hb, len, lay, ahi, alo);

    // ---- layer 1: combined projection (Wf1 | Wb1); A = (ahi, alo) fused ----
    wt_split<<<dim3(G4 / 32, D2 / 32), dim3(32, 8)>>>(Wf1, G4, D2, bhi, blo, 0, 0);
    wt_split<<<dim3(G4 / 32, D2 / 32), dim3(32, 8)>>>(Wb1, G4, D2,
        bhi + (long)G4 * D2, blo + (long)G4 * D2, 0, 0);
    cudaMemcpyAsync(bcat, bf1, G4 * sizeof(float), cudaMemcpyDeviceToDevice);
    cudaMemcpyAsync(bcat + G4, bb1, G4 * sizeof(float), cudaMemcpyDeviceToDevice);
    hgemm<<<dim3(NROW / 128, X4 / 128), 256, HGEMM_SMEM>>>(
        ahi, alo, bhi, blo, bcat, xc, X4, D2, X4, 1.f, 0, 0, 0, 0);

    reset_bar<<<1, 1>>>();
    lstm_scan<<<256, 256, LSTM_SMEM>>>(xc,
                                       Wf1 + (long)D2 * G4, Wb1 + (long)D2 * G4,
                                       h0f + HH, c0f + HH, h0b + HH, c0b + HH,
                                       hf, hb, hcur, len);
    build_lay<<<NROW, 256>>>(hf, hb, len, lay, ehi, elo);  // lay = encoded + split

    // ---- attention ----
    wt_split<<<dim3(D2 / 32, D2 / 32), dim3(32, 8)>>>(Wq, D2, D2, bhi, blo, 0, 0);
    hgemm<<<dim3(NROW / 128, D2 / 128), 256, HGEMM_SMEM>>>(
        ehi, elo, bhi, blo, bq, query, D2, D2, D2, 1.f, 0, 0, 0, 0);
    split_f32<<<(NROW * D2 / 4 + 255) / 256, 256>>>(query, ahi, alo, NROW * D2 / 4);
    hgemm<<<dim3(SS / 128, SS / 128, BB), 256, HGEMM_SMEM>>>(
        ahi, alo, ehi, elo, nullptr, scores, SS, D2, SS, 0.03125f, 0,
        (long)SS * D2, (long)SS * D2, (long)SS * SS);
    softmax_kernel<<<dim3(SS, BB), 256>>>(scores, len);
    wt_split<<<dim3(D2 / 32, SS / 32, BB), dim3(32, 8)>>>(
        lay, D2, SS, bhi, blo, (long)SS * D2, (long)D2 * SS);
    split_f32<<<(BB * SS * SS / 4 + 255) / 256, 256>>>(scores, ahi, alo,
                                                       BB * SS * SS / 4);
    hgemm<<<dim3(SS / 128, D2 / 128, BB), 256, HGEMM_SMEM>>>(
        ahi, alo, bhi, blo, nullptr, ctx, D2, SS, D2, 1.f, 0,
        (long)SS * SS, (long)D2 * SS, (long)SS * D2);
    wt_split<<<dim3(D2 / 32, D2 / 32), dim3(32, 8)>>>(Wao, D2, D2, bhi, blo, 0, 0);
    hgemm<<<dim3(NROW / 128, D2 / 128), 256, HGEMM_SMEM>>>(
        ehi, elo, bhi, blo, bao, pre, D2, D2, D2, 1.f, 0, 0, 0, 0);
    split_f32<<<(NROW * D2 / 4 + 255) / 256, 256>>>(ctx, ahi, alo, NROW * D2 / 4);
    wt_split<<<dim3(D2 / 32, D2 / 32), dim3(32, 8)>>>(Wao + (long)D2 * D2, D2, D2,
                                                      bhi, blo, 0, 0);
    hgemm<<<dim3(NROW / 128, D2 / 128), 256, HGEMM_SMEM>>>(
        ahi, alo, bhi, blo, nullptr, pre, D2, D2, D2, 1.f, 1, 0, 0, 0);
    refine_ln<<<NROW, 256>>>(lay, pre, ln1g, ln1b, len, ahi, alo);

    // ---- head ----
    wt_split<<<dim3(HH / 32, D2 / 32), dim3(32, 8)>>>(Wh, HH, D2, bhi, blo, 0, 0);
    hgemm<<<dim3(NROW / 128, HH / 128), 256, HGEMM_SMEM>>>(
        ahi, alo, bhi, blo, bh, hpre, HH, D2, HH, 1.f, 0, 0, 0, 0);
    head_ln<<<NROW, 256>>>(hpre, ln2g, ln2b, hhi, hlo);

    // ---- vocab projection ----
    hgemm<<<dim3(NROW / 128, VV / 128), 256, HGEMM_SMEM>>>(
        hhi, hlo, wpthi, wptlo, ob, out, VV, HH, VV, 1.f, 0, 0, 0, 0);
}

// round 16
// speedup vs baseline: 1.0566x; 1.0566x over previous
#include <cuda_runtime.h>
#include <cuda_bf16.h>
#include <math.h>
#include <stdint.h>

// ---------------------------------------------------------------------------
// Problem constants: V=32000, E=512, H=512, L=2, B=8, S=512
// ---------------------------------------------------------------------------
#define SS   512
#define BB   8
#define EE   512
#define HH   512
#define D2   1024      // 2H
#define G4   2048      // 4H
#define VV   32000
#define NROW 4096      // B*S
#define X4   (2 * G4)  // combined projection width

// ---------------------------------------------------------------------------
// Device scratch (no cudaMalloc allowed)
// ---------------------------------------------------------------------------
__device__ float g_embx  [NROW * EE];
__device__ float g_xc    [NROW * X4];
__device__ float g_hf    [NROW * HH];
__device__ float g_hb    [NROW * HH];
__device__ float g_lay   [NROW * D2];
__device__ float g_query [NROW * D2];
__device__ float g_scores[BB * SS * SS];
__device__ float g_ctx   [NROW * D2];
__device__ float g_pre   [NROW * D2];
__device__ float g_hpre  [NROW * HH];
__device__ float g_hcur  [2 * 2 * BB * HH];
__device__ float g_bcat  [X4];
__device__ int   g_len   [BB];
__device__ unsigned g_barcnt2[2];

// bf16 split operand buffers
__device__ __nv_bfloat16 g_ahi  [NROW * D2];
__device__ __nv_bfloat16 g_alo  [NROW * D2];
__device__ __nv_bfloat16 g_bhi  [NROW * D2];
__device__ __nv_bfloat16 g_blo  [NROW * D2];
__device__ __nv_bfloat16 g_ehi  [NROW * D2];
__device__ __nv_bfloat16 g_elo  [NROW * D2];
__device__ __nv_bfloat16 g_hhi  [NROW * HH];
__device__ __nv_bfloat16 g_hlo  [NROW * HH];
__device__ __nv_bfloat16 g_wpthi[(long)VV * HH];
__device__ __nv_bfloat16 g_wptlo[(long)VV * HH];

__device__ __forceinline__ float sigm(float x) { return 1.f / (1.f + expf(-x)); }

__device__ __forceinline__ uint32_t smem_u32(const void* p) {
    uint32_t a;
    asm("{ .reg .u64 t; cvta.to.shared.u64 t, %1; cvt.u32.u64 %0, t; }"
        : "=r"(a) : "l"(p));
    return a;
}

__device__ __forceinline__ void mma_bf16(float* c, const uint32_t* a,
                                         const uint32_t* b) {
    asm volatile(
        "mma.sync.aligned.m16n8k16.row.col.f32.bf16.bf16.f32 "
        "{%0,%1,%2,%3}, {%4,%5,%6,%7}, {%8,%9}, {%0,%1,%2,%3};"
        : "+f"(c[0]), "+f"(c[1]), "+f"(c[2]), "+f"(c[3])
        : "r"(a[0]), "r"(a[1]), "r"(a[2]), "r"(a[3]), "r"(b[0]), "r"(b[1]));
}

__device__ __forceinline__ void ldsm_x4(uint32_t& r0, uint32_t& r1,
                                        uint32_t& r2, uint32_t& r3,
                                        uint32_t addr) {
    asm volatile("ldmatrix.sync.aligned.m8n8.x4.shared.b16 {%0,%1,%2,%3}, [%4];"
                 : "=r"(r0), "=r"(r1), "=r"(r2), "=r"(r3) : "r"(addr));
}

#define CP_ASYNC16(dst, src) \
    asm volatile("cp.async.cg.shared.global [%0], [%1], 16;" \
                 :: "r"(dst), "l"(src) : "memory")
#define CP_COMMIT() asm volatile("cp.async.commit_group;" ::: "memory")
#define CP_WAIT0()  asm volatile("cp.async.wait_group 0;" ::: "memory")
#define CP_WAIT1()  asm volatile("cp.async.wait_group 1;" ::: "memory")

// ---------------------------------------------------------------------------
// lengths per batch
// ---------------------------------------------------------------------------
__global__ void len_kernel(const int* __restrict__ x, int* __restrict__ len) {
    __shared__ int red[512];
    int b = blockIdx.x, tid = threadIdx.x;
    red[tid] = (x[b * SS + tid] != 0) ? 1 : 0;
    __syncthreads();
    for (int s = 256; s > 0; s >>= 1) {
        if (tid < s) red[tid] += red[tid + s];
        __syncthreads();
    }
    if (tid == 0) len[b] = red[0];
}

// ---------------------------------------------------------------------------
// embedding gather
// ---------------------------------------------------------------------------
__global__ void embed_kernel(const int* __restrict__ x, const float* __restrict__ emb,
                             float* __restrict__ out) {
    int r = blockIdx.x;
    long tok = (long)x[r];
    float4 v = ((const float4*)(emb + tok * EE))[threadIdx.x];
    ((float4*)(out + (long)r * EE))[threadIdx.x] = v;
}

// ---------------------------------------------------------------------------
// split fp32 -> bf16 hi/lo
// ---------------------------------------------------------------------------
__global__ void split_f32(const float* __restrict__ in,
                          __nv_bfloat16* __restrict__ hi,
                          __nv_bfloat16* __restrict__ lo, int n4) {
    int i = blockIdx.x * blockDim.x + threadIdx.x;
    if (i >= n4) return;
    float4 v = ((const float4*)in)[i];
    __nv_bfloat16 h0 = __float2bfloat16(v.x);
    __nv_bfloat16 h1 = __float2bfloat16(v.y);
    __nv_bfloat16 h2 = __float2bfloat16(v.z);
    __nv_bfloat16 h3 = __float2bfloat16(v.w);
    __nv_bfloat162 ph0 = {h0, h1}, ph1 = {h2, h3};
    __nv_bfloat162 pl0 = {__float2bfloat16(v.x - __bfloat162float(h0)),
                          __float2bfloat16(v.y - __bfloat162float(h1))};
    __nv_bfloat162 pl1 = {__float2bfloat16(v.z - __bfloat162float(h2)),
                          __float2bfloat16(v.w - __bfloat162float(h3))};
    ((__nv_bfloat162*)hi)[i * 2]     = ph0;
    ((__nv_bfloat162*)hi)[i * 2 + 1] = ph1;
    ((__nv_bfloat162*)lo)[i * 2]     = pl0;
    ((__nv_bfloat162*)lo)[i * 2 + 1] = pl1;
}

// ---------------------------------------------------------------------------
// Transpose + split: W[K, N] (row stride ldw) -> T{hi,lo}[N][K]
// ---------------------------------------------------------------------------
__global__ void wt_split(const float* __restrict__ W, int ldw, int K,
                         __nv_bfloat16* __restrict__ Thi,
                         __nv_bfloat16* __restrict__ Tlo,
                         long strW, long strT) {
    __shared__ float tile[32][33];
    W   += (long)blockIdx.z * strW;
    Thi += (long)blockIdx.z * strT;
    Tlo += (long)blockIdx.z * strT;
    int n0 = blockIdx.x * 32, k0 = blockIdx.y * 32;
    int tx = threadIdx.x, ty = threadIdx.y;
#pragma unroll
    for (int i = 0; i < 4; i++)
        tile[ty + i * 8][tx] = W[(long)(k0 + ty + i * 8) * ldw + n0 + tx];
    __syncthreads();
#pragma unroll
    for (int i = 0; i < 4; i++) {
        int n = n0 + ty + i * 8, k = k0 + tx;
        float v = tile[tx][ty + i * 8];
        __nv_bfloat16 hi = __float2bfloat16(v);
        float lo = v - __bfloat162float(hi);
        Thi[(long)n * K + k] = hi;
        Tlo[(long)n * K + k] = __float2bfloat16(lo);
    }
}

// ---------------------------------------------------------------------------
// Generic split-bf16 mma.sync GEMM, cp.async double-buffered (R14 config).
// CTA tile 128x128, K-slab 32, 8 warps (4m x 2n), warp tile 32x64.
// ---------------------------------------------------------------------------
#define WROW 40
#define HS_ARR   (128 * WROW)
#define HS_PERBUF (4 * HS_ARR)
#define HGEMM_SMEM (2 * HS_PERBUF * 2)

__global__ __launch_bounds__(256) void hgemm(
    const __nv_bfloat16* __restrict__ Ahi, const __nv_bfloat16* __restrict__ Alo,
    const __nv_bfloat16* __restrict__ Bhi, const __nv_bfloat16* __restrict__ Blo,
    const float* __restrict__ bias, float* __restrict__ C,
    int N, int K, int ldc, float scale, int accum,
    long strA, long strB, long strC)
{
    extern __shared__ __nv_bfloat16 hs[];
    Ahi += (long)blockIdx.z * strA;  Alo += (long)blockIdx.z * strA;
    Bhi += (long)blockIdx.z * strB;  Blo += (long)blockIdx.z * strB;
    C   += (long)blockIdx.z * strC;

    const int tid  = threadIdx.x;
    const int warp = tid >> 5, lane = tid & 31;
    const int wm = (warp & 3) * 32;
    const int wn = (warp >> 2) * 64;
    const int m0 = blockIdx.x * 128, n0 = blockIdx.y * 128;
    const int nk = K >> 5;

    const int lr = tid >> 1;
    const int lu = (tid & 1) * 16;
    const __nv_bfloat16* gAhi = Ahi + (long)(m0 + lr) * K + lu;
    const __nv_bfloat16* gAlo = Alo + (long)(m0 + lr) * K + lu;
    const __nv_bfloat16* gBhi = Bhi + (long)(n0 + lr) * K + lu;
    const __nv_bfloat16* gBlo = Blo + (long)(n0 + lr) * K + lu;
    const uint32_t sbase = smem_u32(hs);
    const uint32_t so = (lr * WROW + lu) * 2;

    const int a_r = (lane & 15);
    const int a_c = (lane >> 4) << 3;
    const int b_r = ((lane >> 4) << 3) + (lane & 7);
    const int b_c = ((lane >> 3) & 1) << 3;

    float acc[16][4];
#pragma unroll
    for (int i = 0; i < 16; i++)
#pragma unroll
        for (int j = 0; j < 4; j++) acc[i][j] = 0.f;

#define ISSUE(kb, buf)                                                       \
    do {                                                                     \
        const int _ko = (kb) * 32;                                           \
        uint32_t _d = sbase + (uint32_t)(buf) * (HS_PERBUF * 2) + so;        \
        CP_ASYNC16(_d,                  gAhi + _ko);                         \
        CP_ASYNC16(_d + 16,             gAhi + _ko + 8);                     \
        CP_ASYNC16(_d + HS_ARR * 2,     gAlo + _ko);                         \
        CP_ASYNC16(_d + HS_ARR * 2 + 16, gAlo + _ko + 8);                    \
        CP_ASYNC16(_d + HS_ARR * 4,     gBhi + _ko);                         \
        CP_ASYNC16(_d + HS_ARR * 4 + 16, gBhi + _ko + 8);                    \
        CP_ASYNC16(_d + HS_ARR * 6,     gBlo + _ko);                         \
        CP_ASYNC16(_d + HS_ARR * 6 + 16, gBlo + _ko + 8);                    \
    } while (0)

    ISSUE(0, 0);
    CP_COMMIT();

    for (int kb = 0; kb < nk; kb++) {
        if (kb + 1 < nk) {
            ISSUE(kb + 1, (kb + 1) & 1);
            CP_COMMIT();
            CP_WAIT1();
        } else {
            CP_WAIT0();
        }
        __syncthreads();

        const uint32_t bufb = sbase + (uint32_t)(kb & 1) * (HS_PERBUF * 2);
#pragma unroll
        for (int kh = 0; kh < 32; kh += 16) {
            uint32_t ah[2][4], al[2][4];
#pragma unroll
            for (int mt = 0; mt < 2; mt++) {
                uint32_t off = bufb + ((wm + mt * 16 + a_r) * WROW + kh + a_c) * 2;
                ldsm_x4(ah[mt][0], ah[mt][1], ah[mt][2], ah[mt][3], off);
                ldsm_x4(al[mt][0], al[mt][1], al[mt][2], al[mt][3],
                        off + HS_ARR * 2);
            }
            uint32_t bh[8][2], bl[8][2];
#pragma unroll
            for (int p = 0; p < 4; p++) {
                uint32_t off = bufb + HS_ARR * 4 +
                               ((wn + p * 16 + b_r) * WROW + kh + b_c) * 2;
                ldsm_x4(bh[p * 2][0], bh[p * 2][1], bh[p * 2 + 1][0],
                        bh[p * 2 + 1][1], off);
                ldsm_x4(bl[p * 2][0], bl[p * 2][1], bl[p * 2 + 1][0],
                        bl[p * 2 + 1][1], off + HS_ARR * 2);
            }
#pragma unroll
            for (int mt = 0; mt < 2; mt++)
#pragma unroll
                for (int nt = 0; nt < 8; nt++) {
                    float* c = acc[mt * 8 + nt];
                    mma_bf16(c, ah[mt], bh[nt]);
                    mma_bf16(c, ah[mt], bl[nt]);
                    mma_bf16(c, al[mt], bh[nt]);
                }
        }
        __syncthreads();
    }
#undef ISSUE

    const int g  = lane >> 2;
    const int c2 = (lane & 3) * 2;
#pragma unroll
    for (int nt = 0; nt < 8; nt++) {
        const int col = n0 + wn + nt * 8 + c2;
        float b0 = 0.f, b1 = 0.f;
        if (bias) { b0 = bias[col]; b1 = bias[col + 1]; }
#pragma unroll
        for (int mt = 0; mt < 2; mt++) {
            const float* c = acc[mt * 8 + nt];
            const int r0 = m0 + wm + mt * 16 + g;
            long o0 = (long)r0 * ldc + col;
            long o1 = (long)(r0 + 8) * ldc + col;
            float2 v0 = make_float2(c[0] * scale + b0, c[1] * scale + b1);
            float2 v1 = make_float2(c[2] * scale + b0, c[3] * scale + b1);
            if (accum) {
                float2 e0 = *(const float2*)(C + o0);
                float2 e1 = *(const float2*)(C + o1);
                v0.x += e0.x; v0.y += e0.y; v1.x += e1.x; v1.y += e1.y;
            }
            *(float2*)(C + o0) = v0;
            *(float2*)(C + o1) = v1;
        }
    }
}

// ---------------------------------------------------------------------------
// Masked softmax per (b, q) row
// ---------------------------------------------------------------------------
__global__ void softmax_kernel(float* __restrict__ sc, const int* __restrict__ len) {
    const int q = blockIdx.x, b = blockIdx.y;
    float* row = sc + ((long)b * SS + q) * SS;
    const int L = len[b];
    const int t = threadIdx.x;
    __shared__ float red[256];
    if (q >= L) {
        for (int i = t; i < SS; i += 256) row[i] = 0.f;
        return;
    }
    float m = -3.402823466e38f;
    for (int i = t; i < L; i += 256) m = fmaxf(m, row[i]);
    red[t] = m; __syncthreads();
    for (int s = 128; s > 0; s >>= 1) {
        if (t < s) red[t] = fmaxf(red[t], red[t + s]);
        __syncthreads();
    }
    m = red[0]; __syncthreads();
    float sum = 0.f;
    for (int i = t; i < L; i += 256) sum += expf(row[i] - m);
    red[t] = sum; __syncthreads();
    for (int s = 128; s > 0; s >>= 1) {
        if (t < s) red[t] += red[t + s];
        __syncthreads();
    }
    float inv = 1.f / red[0];
    for (int i = t; i < SS; i += 256)
        row[i] = (i < L) ? expf(row[i] - m) * inv : 0.f;
}

// ---------------------------------------------------------------------------
// Build layer input + fused bf16 hi/lo split
// ---------------------------------------------------------------------------
__global__ void build_lay(const float* __restrict__ hf, const float* __restrict__ hb,
                          const int* __restrict__ len, float* __restrict__ lay,
                          __nv_bfloat16* __restrict__ shi,
                          __nv_bfloat16* __restrict__ slo) {
    int r = blockIdx.x;
    int b = r >> 9, tt = r & 511;
    int active = tt < len[b];
    int t = threadIdx.x;
    for (int i = t; i < D2; i += 256) {
        float v = 0.f;
        if (active) v = (i < HH) ? hf[(long)r * HH + i] : hb[(long)r * HH + i - HH];
        lay[(long)r * D2 + i] = v;
        __nv_bfloat16 hi = __float2bfloat16(v);
        shi[(long)r * D2 + i] = hi;
        slo[(long)r * D2 + i] = __float2bfloat16(v - __bfloat162float(hi));
    }
}

// ---------------------------------------------------------------------------
// refined = LN(encoded + tanh(pre)) masked; emits bf16 hi/lo only
// ---------------------------------------------------------------------------
__global__ void refine_ln(const float* __restrict__ enc, const float* __restrict__ pre,
                          const float* __restrict__ g, const float* __restrict__ bta,
                          const int* __restrict__ len,
                          __nv_bfloat16* __restrict__ shi,
                          __nv_bfloat16* __restrict__ slo) {
    int r = blockIdx.x;
    int b = r >> 9, tt = r & 511;
    int t = threadIdx.x;
    __shared__ float r1[256], r2[256];
    float v[4];
    float s = 0.f, s2 = 0.f;
#pragma unroll
    for (int i = 0; i < 4; i++) {
        int idx = t + i * 256;
        float xx = enc[(long)r * D2 + idx] + tanhf(pre[(long)r * D2 + idx]);
        v[i] = xx; s += xx; s2 += xx * xx;
    }
    r1[t] = s; r2[t] = s2; __syncthreads();
    for (int st = 128; st > 0; st >>= 1) {
        if (t < st) { r1[t] += r1[t + st]; r2[t] += r2[t + st]; }
        __syncthreads();
    }
    float mean = r1[0] * (1.f / 1024.f);
    float var = r2[0] * (1.f / 1024.f) - mean * mean;
    float inv = rsqrtf(var + 1e-5f);
    int active = tt < len[b];
#pragma unroll
    for (int i = 0; i < 4; i++) {
        int idx = t + i * 256;
        float o = (v[i] - mean) * inv * g[idx] + bta[idx];
        o = active ? o : 0.f;
        __nv_bfloat16 hi = __float2bfloat16(o);
        shi[(long)r * D2 + idx] = hi;
        slo[(long)r * D2 + idx] = __float2bfloat16(o - __bfloat162float(hi));
    }
}

// ---------------------------------------------------------------------------
// head = LN(gelu_exact(hpre)) -> emit bf16 hi/lo split
// ---------------------------------------------------------------------------
__global__ void head_ln(const float* __restrict__ hpre, const float* __restrict__ g,
                        const float* __restrict__ bta,
                        __nv_bfloat16* __restrict__ hhi,
                        __nv_bfloat16* __restrict__ hlo) {
    int r = blockIdx.x;
    int t = threadIdx.x;
    __shared__ float r1[256], r2[256];
    float v[2];
    float s = 0.f, s2 = 0.f;
#pragma unroll
    for (int i = 0; i < 2; i++) {
        int idx = t + i * 256;
        float xx = hpre[(long)r * HH + idx];
        float ge = 0.5f * xx * (1.f + erff(xx * 0.70710678118654752f));
        v[i] = ge; s += ge; s2 += ge * ge;
    }
    r1[t] = s; r2[t] = s2; __syncthreads();
    for (int st = 128; st > 0; st >>= 1) {
        if (t < st) { r1[t] += r1[t + st]; r2[t] += r2[t + st]; }
        __syncthreads();
    }
    float mean = r1[0] * (1.f / 512.f);
    float var = r2[0] * (1.f / 512.f) - mean * mean;
    float inv = rsqrtf(var + 1e-5f);
#pragma unroll
    for (int i = 0; i < 2; i++) {
        int idx = t + i * 256;
        float o = (v[i] - mean) * inv * g[idx] + bta[idx];
        __nv_bfloat16 hi = __float2bfloat16(o);
        float lo = o - __bfloat162float(hi);
        hhi[(long)r * HH + idx] = hi;
        hlo[(long)r * HH + idx] = __float2bfloat16(lo);
    }
}

// ---------------------------------------------------------------------------
// Reset grid barrier counters
// ---------------------------------------------------------------------------
__global__ void reset_bar() { g_barcnt2[0] = 0u; g_barcnt2[1] = 0u; }

// ---------------------------------------------------------------------------
// Persistent BiLSTM scan — tensor-core GEMV (unchanged; xp row stride X4)
// ---------------------------------------------------------------------------
#define LROW 520
#define LS_W   (16 * LROW)
#define LSTM_SMEM (4 * LS_W * 2 + 1024 * 4 + 128 * 4 + 32 * 4)

__global__ __launch_bounds__(256, 2) void lstm_scan(
    const float* __restrict__ xc,
    const float* __restrict__ Wrf, const float* __restrict__ Wrb,
    const float* __restrict__ h0f, const float* __restrict__ c0f,
    const float* __restrict__ h0b, const float* __restrict__ c0b,
    float* __restrict__ houtf, float* __restrict__ houtb,
    float* __restrict__ hcur, const int* __restrict__ len)
{
    extern __shared__ char smraw[];
    __nv_bfloat16* sWhi = (__nv_bfloat16*)smraw;
    __nv_bfloat16* sWlo = sWhi + LS_W;
    __nv_bfloat16* sAhi = sWlo + LS_W;
    __nv_bfloat16* sAlo = sAhi + LS_W;
    float* part  = (float*)(sAlo + LS_W);
    float* gates = part + 1024;
    float* cst   = gates + 128;

    const int tid  = threadIdx.x;
    const int warp = tid >> 5, lane = tid & 31;
    const int dir = blockIdx.x >> 7;
    const int kb  = blockIdx.x & 127;
    const int j0  = kb * 4;
    const float* Wr = dir ? Wrb : Wrf;
    const float* xp = xc + dir * G4;
    const float* h0 = dir ? h0b : h0f;
    const float* c0 = dir ? c0b : c0f;
    float* hout  = dir ? houtb : houtf;
    float* hbase = hcur + dir * (2 * BB * HH);
    volatile unsigned* barp = &g_barcnt2[dir];

    {
        int col = tid & 15;
        int gcol = (col >> 2) * 512 + j0 + (col & 3);
        for (int k = tid >> 4; k < 512; k += 16) {
            float v = Wr[(long)k * G4 + gcol];
            __nv_bfloat16 hi = __float2bfloat16(v);
            sWhi[col * LROW + k] = hi;
            sWlo[col * LROW + k] = __float2bfloat16(v - __bfloat162float(hi));
        }
    }
    for (int f = tid; f < 8 * LROW; f += 256) {
        sAhi[8 * LROW + f] = __float2bfloat16(0.f);
        sAlo[8 * LROW + f] = __float2bfloat16(0.f);
    }
    if (tid < 32) {
        int u = tid >> 3, b = tid & 7;
        cst[u * 8 + b] = c0[j0 + u];
        __stcg(&hbase[(j0 + u) * 8 + b], h0[j0 + u]);
    }

    const uint32_t sAhiB = smem_u32(sAhi), sAloB = smem_u32(sAlo);
    const uint32_t sWhiB = smem_u32(sWhi), sWloB = smem_u32(sWlo);
    const int kbase = warp * 64;
    const uint32_t aoff = ((lane & 15) * LROW + kbase + ((lane >> 4) << 3)) * 2;
    const uint32_t boff = ((((lane >> 4) << 3) + (lane & 7)) * LROW + kbase +
                          (((lane >> 3) & 1) << 3)) * 2;

    unsigned phase = 1;
#define GRIDBAR()                                                         \
    do {                                                                  \
        __syncthreads();                                                  \
        if (tid == 0) {                                                   \
            __threadfence();                                              \
            atomicAdd((unsigned*)barp, 1u);                               \
            unsigned tgt = 128u * phase;                                  \
            while (*barp < tgt) {}                                        \
        }                                                                 \
        __syncthreads();                                                  \
        phase++;                                                          \
    } while (0)

    GRIDBAR();

    for (int s = 0; s < SS; s++) {
        const float* hrd = hbase + (s & 1) * (BB * HH);
        float* hwr = hbase + ((s + 1) & 1) * (BB * HH);
        const int t_real = dir ? (SS - 1 - s) : s;

        float xpv = 0.f;
        if (tid < 128) {
            int col = tid >> 3, b = tid & 7;
            xpv = __ldg(&xp[((long)(b * SS + t_real)) * X4 +
                            (col >> 2) * 512 + j0 + (col & 3)]);
        }
        float hpv = 0.f;
        if (tid < 32)
            hpv = __ldcg(&hrd[(j0 + (tid >> 3)) * 8 + (tid & 7)]);

        {
            int b = tid & 7, kp = tid >> 3;
#pragma unroll
            for (int i = 0; i < 8; i++) {
                int k = (kp + 32 * i) * 2;
                float v0 = __ldcg(hrd + k * 8 + b);
                float v1 = __ldcg(hrd + (k + 1) * 8 + b);
                __nv_bfloat16 hh0 = __float2bfloat16(v0);
                __nv_bfloat16 hh1 = __float2bfloat16(v1);
                __nv_bfloat162 ph = {hh0, hh1};
                __nv_bfloat162 pl = {__float2bfloat16(v0 - __bfloat162float(hh0)),
                                     __float2bfloat16(v1 - __bfloat162float(hh1))};
                *(__nv_bfloat162*)&sAhi[b * LROW + k] = ph;
                *(__nv_bfloat162*)&sAlo[b * LROW + k] = pl;
            }
        }
        __syncthreads();

        float acA[2][4], acB[2][4];
#pragma unroll
        for (int nt = 0; nt < 2; nt++)
#pragma unroll
            for (int j = 0; j < 4; j++) { acA[nt][j] = 0.f; acB[nt][j] = 0.f; }
#pragma unroll
        for (int kk = 0; kk < 4; kk++) {
            uint32_t ah[4], al[4], bh4[4], bl4[4];
            ldsm_x4(ah[0], ah[1], ah[2], ah[3], sAhiB + aoff + kk * 32);
            ldsm_x4(al[0], al[1], al[2], al[3], sAloB + aoff + kk * 32);
            ldsm_x4(bh4[0], bh4[1], bh4[2], bh4[3], sWhiB + boff + kk * 32);
            ldsm_x4(bl4[0], bl4[1], bl4[2], bl4[3], sWloB + boff + kk * 32);
            float (*ac)[4] = (kk & 1) ? acB : acA;
            uint32_t bh0[2] = {bh4[0], bh4[1]}, bh1[2] = {bh4[2], bh4[3]};
            uint32_t bl0[2] = {bl4[0], bl4[1]}, bl1[2] = {bl4[2], bl4[3]};
            mma_bf16(ac[0], ah, bh0);
            mma_bf16(ac[0], ah, bl0);
            mma_bf16(ac[0], al, bh0);
            mma_bf16(ac[1], ah, bh1);
            mma_bf16(ac[1], ah, bl1);
            mma_bf16(ac[1], al, bh1);
        }
        {
            int g = lane >> 2, c2 = (lane & 3) * 2;
#pragma unroll
            for (int nt = 0; nt < 2; nt++) {
                part[warp * 128 + (nt * 8 + c2) * 8 + g]     = acA[nt][0] + acB[nt][0];
                part[warp * 128 + (nt * 8 + c2 + 1) * 8 + g] = acA[nt][1] + acB[nt][1];
            }
        }
        __syncthreads();

        if (tid < 128) {
            float ssum = xpv;
#pragma unroll
            for (int w = 0; w < 8; w++) ssum += part[w * 128 + tid];
            gates[tid] = ssum;
        }
        __syncthreads();

        if (tid < 32) {
            int u = tid >> 3, b = tid & 7;
            float ig = gates[(u) * 8 + b];
            float fg = gates[(4 + u) * 8 + b];
            float og = gates[(8 + u) * 8 + b];
            float gg = gates[(12 + u) * 8 + b];
            float cp = cst[u * 8 + b];
            float cn = sigm(fg) * cp + sigm(ig) * tanhf(gg);
            float hn = sigm(og) * tanhf(cn);
            int active = t_real < len[b];
            float h = active ? hn : hpv;
            float c = active ? cn : cp;
            cst[u * 8 + b] = c;
            __stcg(&hwr[(j0 + u) * 8 + b], h);
            hout[((long)(b * SS + t_real)) * HH + j0 + u] = h;
        }
        GRIDBAR();
    }
#undef GRIDBAR
}

// ---------------------------------------------------------------------------
// Host driver
// ---------------------------------------------------------------------------
extern "C" void kernel_launch(void* const* d_in, const int* in_sizes, int n_in,
                              void* d_out, int out_size) {
    const int*   x    = (const int*)  d_in[0];
    const float* emb  = (const float*)d_in[1];
    const float* Wf0  = (const float*)d_in[2];
    const float* bf0  = (const float*)d_in[3];
    const float* Wb0  = (const float*)d_in[4];
    const float* bb0  = (const float*)d_in[5];
    const float* Wf1  = (const float*)d_in[6];
    const float* bf1  = (const float*)d_in[7];
    const float* Wb1  = (const float*)d_in[8];
    const float* bb1  = (const float*)d_in[9];
    const float* h0f  = (const float*)d_in[10];
    const float* c0f  = (const float*)d_in[11];
    const float* h0b  = (const float*)d_in[12];
    const float* c0b  = (const float*)d_in[13];
    const float* Wq   = (const float*)d_in[14];
    const float* bq   = (const float*)d_in[15];
    const float* Wao  = (const float*)d_in[16];
    const float* bao  = (const float*)d_in[17];
    const float* ln1g = (const float*)d_in[18];
    const float* ln1b = (const float*)d_in[19];
    const float* Wh   = (const float*)d_in[20];
    const float* bh   = (const float*)d_in[21];
    const float* ln2g = (const float*)d_in[22];
    const float* ln2b = (const float*)d_in[23];
    const float* Wp   = (const float*)d_in[24];
    const float* ob   = (const float*)d_in[25];
    float* out = (float*)d_out;

    float *embx, *xc, *hf, *hb, *lay, *query, *scores, *ctx, *pre,
          *hpre, *hcur, *bcat;
    __nv_bfloat16 *ahi, *alo, *bhi, *blo, *ehi, *elo, *hhi, *hlo, *wpthi, *wptlo;
    int* len;
    cudaGetSymbolAddress((void**)&embx,   g_embx);
    cudaGetSymbolAddress((void**)&xc,     g_xc);
    cudaGetSymbolAddress((void**)&hf,     g_hf);
    cudaGetSymbolAddress((void**)&hb,     g_hb);
    cudaGetSymbolAddress((void**)&lay,    g_lay);
    cudaGetSymbolAddress((void**)&query,  g_query);
    cudaGetSymbolAddress((void**)&scores, g_scores);
    cudaGetSymbolAddress((void**)&ctx,    g_ctx);
    cudaGetSymbolAddress((void**)&pre,    g_pre);
    cudaGetSymbolAddress((void**)&hpre,   g_hpre);
    cudaGetSymbolAddress((void**)&hcur,   g_hcur);
    cudaGetSymbolAddress((void**)&bcat,   g_bcat);
    cudaGetSymbolAddress((void**)&len,    g_len);
    cudaGetSymbolAddress((void**)&ahi,    g_ahi);
    cudaGetSymbolAddress((void**)&alo,    g_alo);
    cudaGetSymbolAddress((void**)&bhi,    g_bhi);
    cudaGetSymbolAddress((void**)&blo,    g_blo);
    cudaGetSymbolAddress((void**)&ehi,    g_ehi);
    cudaGetSymbolAddress((void**)&elo,    g_elo);
    cudaGetSymbolAddress((void**)&hhi,    g_hhi);
    cudaGetSymbolAddress((void**)&hlo,    g_hlo);
    cudaGetSymbolAddress((void**)&wpthi,  g_wpthi);
    cudaGetSymbolAddress((void**)&wptlo,  g_wptlo);

    cudaFuncSetAttribute(lstm_scan, cudaFuncAttributeMaxDynamicSharedMemorySize,
                         LSTM_SMEM);
    cudaFuncSetAttribute(hgemm, cudaFuncAttributeMaxDynamicSharedMemorySize,
                         HGEMM_SMEM);

    len_kernel<<<BB, 512>>>(x, len);
    embed_kernel<<<NROW, 128>>>(x, emb, embx);
    wt_split<<<dim3(VV / 32, HH / 32), dim3(32, 8)>>>(Wp, VV, HH, wpthi, wptlo, 0, 0);

    // ---- layer 0: combined projection (Wf0 | Wb0), N = 4096 ----
    split_f32<<<(NROW * EE / 4 + 255) / 256, 256>>>(embx, ahi, alo, NROW * EE / 4);
    wt_split<<<dim3(G4 / 32, EE / 32), dim3(32, 8)>>>(Wf0, G4, EE, bhi, blo, 0, 0);
    wt_split<<<dim3(G4 / 32, EE / 32), dim3(32, 8)>>>(Wb0, G4, EE,
        bhi + (long)G4 * EE, blo + (long)G4 * EE, 0, 0);
    cudaMemcpyAsync(bcat, bf0, G4 * sizeof(float), cudaMemcpyDeviceToDevice);
    cudaMemcpyAsync(bcat + G4, bb0, G4 * sizeof(float), cudaMemcpyDeviceToDevice);
    hgemm<<<dim3(NROW / 128, X4 / 128), 256, HGEMM_SMEM>>>(
        ahi, alo, bhi, blo, bcat, xc, X4, EE, X4, 1.f, 0, 0, 0, 0);

    reset_bar<<<1, 1>>>();
    lstm_scan<<<256, 256, LSTM_SMEM>>>(xc,
                                       Wf0 + (long)EE * G4, Wb0 + (long)EE * G4,
                                       h0f, c0f, h0b, c0b, hf, hb, hcur, len);
    build_lay<<<NROW, 256>>>(hf, hb, len, lay, ahi, alo);

    // ---- layer 1: combined projection (Wf1 | Wb1); A = (ahi, alo) fused ----
    wt_split<<<dim3(G4 / 32, D2 / 32), dim3(32, 8)>>>(Wf1, G4, D2, bhi, blo, 0, 0);
    wt_split<<<dim3(G4 / 32, D2 / 32), dim3(32, 8)>>>(Wb1, G4, D2,
        bhi + (long)G4 * D2, blo + (long)G4 * D2, 0, 0);
    cudaMemcpyAsync(bcat, bf1, G4 * sizeof(float), cudaMemcpyDeviceToDevice);
    cudaMemcpyAsync(bcat + G4, bb1, G4 * sizeof(float), cudaMemcpyDeviceToDevice);
    hgemm<<<dim3(NROW / 128, X4 / 128), 256, HGEMM_SMEM>>>(
        ahi, alo, bhi, blo, bcat, xc, X4, D2, X4, 1.f, 0, 0, 0, 0);

    reset_bar<<<1, 1>>>();
    lstm_scan<<<256, 256, LSTM_SMEM>>>(xc,
                                       Wf1 + (long)D2 * G4, Wb1 + (long)D2 * G4,
                                       h0f + HH, c0f + HH, h0b + HH, c0b + HH,
                                       hf, hb, hcur, len);
    build_lay<<<NROW, 256>>>(hf, hb, len, lay, ehi, elo);  // lay = encoded + split

    // ---- attention ----
    wt_split<<<dim3(D2 / 32, D2 / 32), dim3(32, 8)>>>(Wq, D2, D2, bhi, blo, 0, 0);
    hgemm<<<dim3(NROW / 128, D2 / 128), 256, HGEMM_SMEM>>>(
        ehi, elo, bhi, blo, bq, query, D2, D2, D2, 1.f, 0, 0, 0, 0);
    split_f32<<<(NROW * D2 / 4 + 255) / 256, 256>>>(query, ahi, alo, NROW * D2 / 4);
    hgemm<<<dim3(SS / 128, SS / 128, BB), 256, HGEMM_SMEM>>>(
        ahi, alo, ehi, elo, nullptr, scores, SS, D2, SS, 0.03125f, 0,
        (long)SS * D2, (long)SS * D2, (long)SS * SS);
    softmax_kernel<<<dim3(SS, BB), 256>>>(scores, len);
    wt_split<<<dim3(D2 / 32, SS / 32, BB), dim3(32, 8)>>>(
        lay, D2, SS, bhi, blo, (long)SS * D2, (long)D2 * SS);
    split_f32<<<(BB * SS * SS / 4 + 255) / 256, 256>>>(scores, ahi, alo,
                                                       BB * SS * SS / 4);
    hgemm<<<dim3(SS / 128, D2 / 128, BB), 256, HGEMM_SMEM>>>(
        ahi, alo, bhi, blo, nullptr, ctx, D2, SS, D2, 1.f, 0,
        (long)SS * SS, (long)D2 * SS, (long)SS * D2);
    wt_split<<<dim3(D2 / 32, D2 / 32), dim3(32, 8)>>>(Wao, D2, D2, bhi, blo, 0, 0);
    hgemm<<<dim3(NROW / 128, D2 / 128), 256, HGEMM_SMEM>>>(
        ehi, elo, bhi, blo, bao, pre, D2, D2, D2, 1.f, 0, 0, 0, 0);
    split_f32<<<(NROW * D2 / 4 + 255) / 256, 256>>>(ctx, ahi, alo, NROW * D2 / 4);
    wt_split<<<dim3(D2 / 32, D2 / 32), dim3(32, 8)>>>(Wao + (long)D2 * D2, D2, D2,
                                                      bhi, blo, 0, 0);
    hgemm<<<dim3(NROW / 128, D2 / 128), 256, HGEMM_SMEM>>>(
        ahi, alo, bhi, blo, nullptr, pre, D2, D2, D2, 1.f, 1, 0, 0, 0);
    refine_ln<<<NROW, 256>>>(lay, pre, ln1g, ln1b, len, ahi, alo);

    // ---- head ----
    wt_split<<<dim3(HH / 32, D2 / 32), dim3(32, 8)>>>(Wh, HH, D2, bhi, blo, 0, 0);
    hgemm<<<dim3(NROW / 128, HH / 128), 256, HGEMM_SMEM>>>(
        ahi, alo, bhi, blo, bh, hpre, HH, D2, HH, 1.f, 0, 0, 0, 0);
    head_ln<<<NROW, 256>>>(hpre, ln2g, ln2b, hhi, hlo);

    // ---- vocab projection ----
    hgemm<<<dim3(NROW / 128, VV / 128), 256, HGEMM_SMEM>>>(
        hhi, hlo, wpthi, wptlo, ob, out, VV, HH, VV, 1.f, 0, 0, 0, 0);
}

// round 17
// speedup vs baseline: 1.0651x; 1.0081x over previous
#include <cuda_runtime.h>
#include <cuda_bf16.h>
#include <math.h>
#include <stdint.h>

// ---------------------------------------------------------------------------
// Problem constants: V=32000, E=512, H=512, L=2, B=8, S=512
// ---------------------------------------------------------------------------
#define SS   512
#define BB   8
#define EE   512
#define HH   512
#define D2   1024      // 2H
#define G4   2048      // 4H
#define VV   32000
#define NROW 4096      // B*S
#define X4   (2 * G4)  // combined projection width

// ---------------------------------------------------------------------------
// Device scratch (no cudaMalloc allowed)
// ---------------------------------------------------------------------------
__device__ float g_xc    [NROW * X4];
__device__ float g_hf    [NROW * HH];
__device__ float g_hb    [NROW * HH];
__device__ float g_lay   [NROW * D2];
__device__ float g_scores[BB * SS * SS];
__device__ float g_pre   [NROW * D2];
__device__ float g_hpre  [NROW * HH];
__device__ float g_hcur  [2 * 2 * BB * HH];
__device__ float g_bcat  [X4];
__device__ int   g_len   [BB];
__device__ unsigned g_barcnt2[2];

// bf16 split operand buffers
__device__ __nv_bfloat16 g_ahi  [NROW * D2];
__device__ __nv_bfloat16 g_alo  [NROW * D2];
__device__ __nv_bfloat16 g_bhi  [NROW * D2];
__device__ __nv_bfloat16 g_blo  [NROW * D2];
__device__ __nv_bfloat16 g_ehi  [NROW * D2];
__device__ __nv_bfloat16 g_elo  [NROW * D2];
__device__ __nv_bfloat16 g_hhi  [NROW * HH];
__device__ __nv_bfloat16 g_hlo  [NROW * HH];
__device__ __nv_bfloat16 g_wpthi[(long)VV * HH];
__device__ __nv_bfloat16 g_wptlo[(long)VV * HH];

__device__ __forceinline__ float sigm(float x) { return 1.f / (1.f + expf(-x)); }

__device__ __forceinline__ uint32_t smem_u32(const void* p) {
    uint32_t a;
    asm("{ .reg .u64 t; cvta.to.shared.u64 t, %1; cvt.u32.u64 %0, t; }"
        : "=r"(a) : "l"(p));
    return a;
}

__device__ __forceinline__ void mma_bf16(float* c, const uint32_t* a,
                                         const uint32_t* b) {
    asm volatile(
        "mma.sync.aligned.m16n8k16.row.col.f32.bf16.bf16.f32 "
        "{%0,%1,%2,%3}, {%4,%5,%6,%7}, {%8,%9}, {%0,%1,%2,%3};"
        : "+f"(c[0]), "+f"(c[1]), "+f"(c[2]), "+f"(c[3])
        : "r"(a[0]), "r"(a[1]), "r"(a[2]), "r"(a[3]), "r"(b[0]), "r"(b[1]));
}

__device__ __forceinline__ void ldsm_x4(uint32_t& r0, uint32_t& r1,
                                        uint32_t& r2, uint32_t& r3,
                                        uint32_t addr) {
    asm volatile("ldmatrix.sync.aligned.m8n8.x4.shared.b16 {%0,%1,%2,%3}, [%4];"
                 : "=r"(r0), "=r"(r1), "=r"(r2), "=r"(r3) : "r"(addr));
}

#define CP_ASYNC16(dst, src) \
    asm volatile("cp.async.cg.shared.global [%0], [%1], 16;" \
                 :: "r"(dst), "l"(src) : "memory")
#define CP_COMMIT() asm volatile("cp.async.commit_group;" ::: "memory")
#define CP_WAIT0()  asm volatile("cp.async.wait_group 0;" ::: "memory")
#define CP_WAIT1()  asm volatile("cp.async.wait_group 1;" ::: "memory")

// ---------------------------------------------------------------------------
// lengths per batch
// ---------------------------------------------------------------------------
__global__ void len_kernel(const int* __restrict__ x, int* __restrict__ len) {
    __shared__ int red[512];
    int b = blockIdx.x, tid = threadIdx.x;
    red[tid] = (x[b * SS + tid] != 0) ? 1 : 0;
    __syncthreads();
    for (int s = 256; s > 0; s >>= 1) {
        if (tid < s) red[tid] += red[tid + s];
        __syncthreads();
    }
    if (tid == 0) len[b] = red[0];
}

// ---------------------------------------------------------------------------
// embedding gather + fused bf16 hi/lo split (emits split only)
// ---------------------------------------------------------------------------
__global__ void embed_kernel(const int* __restrict__ x, const float* __restrict__ emb,
                             __nv_bfloat16* __restrict__ shi,
                             __nv_bfloat16* __restrict__ slo) {
    int r = blockIdx.x;
    long tok = (long)x[r];
    float4 v = ((const float4*)(emb + tok * EE))[threadIdx.x];
    long o = (long)r * EE + threadIdx.x * 4;
    __nv_bfloat16 h0 = __float2bfloat16(v.x);
    __nv_bfloat16 h1 = __float2bfloat16(v.y);
    __nv_bfloat16 h2 = __float2bfloat16(v.z);
    __nv_bfloat16 h3 = __float2bfloat16(v.w);
    __nv_bfloat162 ph0 = {h0, h1}, ph1 = {h2, h3};
    __nv_bfloat162 pl0 = {__float2bfloat16(v.x - __bfloat162float(h0)),
                          __float2bfloat16(v.y - __bfloat162float(h1))};
    __nv_bfloat162 pl1 = {__float2bfloat16(v.z - __bfloat162float(h2)),
                          __float2bfloat16(v.w - __bfloat162float(h3))};
    *(__nv_bfloat162*)(shi + o)     = ph0;
    *(__nv_bfloat162*)(shi + o + 2) = ph1;
    *(__nv_bfloat162*)(slo + o)     = pl0;
    *(__nv_bfloat162*)(slo + o + 2) = pl1;
}

// ---------------------------------------------------------------------------
// Transpose + split: W[K, N] (row stride ldw) -> T{hi,lo}[N][K]
// ---------------------------------------------------------------------------
__global__ void wt_split(const float* __restrict__ W, int ldw, int K,
                         __nv_bfloat16* __restrict__ Thi,
                         __nv_bfloat16* __restrict__ Tlo,
                         long strW, long strT) {
    __shared__ float tile[32][33];
    W   += (long)blockIdx.z * strW;
    Thi += (long)blockIdx.z * strT;
    Tlo += (long)blockIdx.z * strT;
    int n0 = blockIdx.x * 32, k0 = blockIdx.y * 32;
    int tx = threadIdx.x, ty = threadIdx.y;
#pragma unroll
    for (int i = 0; i < 4; i++)
        tile[ty + i * 8][tx] = W[(long)(k0 + ty + i * 8) * ldw + n0 + tx];
    __syncthreads();
#pragma unroll
    for (int i = 0; i < 4; i++) {
        int n = n0 + ty + i * 8, k = k0 + tx;
        float v = tile[tx][ty + i * 8];
        __nv_bfloat16 hi = __float2bfloat16(v);
        float lo = v - __bfloat162float(hi);
        Thi[(long)n * K + k] = hi;
        Tlo[(long)n * K + k] = __float2bfloat16(lo);
    }
}

// ---------------------------------------------------------------------------
// Generic split-bf16 mma.sync GEMM, cp.async double-buffered (R14 config)
// plus optional bf16 hi/lo output epilogue (outsplit).
// CTA tile 128x128, K-slab 32, 8 warps (4m x 2n), warp tile 32x64.
// ---------------------------------------------------------------------------
#define WROW 40
#define HS_ARR   (128 * WROW)
#define HS_PERBUF (4 * HS_ARR)
#define HGEMM_SMEM (2 * HS_PERBUF * 2)

__global__ __launch_bounds__(256) void hgemm(
    const __nv_bfloat16* __restrict__ Ahi, const __nv_bfloat16* __restrict__ Alo,
    const __nv_bfloat16* __restrict__ Bhi, const __nv_bfloat16* __restrict__ Blo,
    const float* __restrict__ bias, float* __restrict__ C,
    int N, int K, int ldc, float scale, int accum,
    long strA, long strB, long strC,
    __nv_bfloat16* __restrict__ Chi, __nv_bfloat16* __restrict__ Clo,
    int outsplit)
{
    extern __shared__ __nv_bfloat16 hs[];
    Ahi += (long)blockIdx.z * strA;  Alo += (long)blockIdx.z * strA;
    Bhi += (long)blockIdx.z * strB;  Blo += (long)blockIdx.z * strB;
    if (!outsplit) C += (long)blockIdx.z * strC;
    else { Chi += (long)blockIdx.z * strC; Clo += (long)blockIdx.z * strC; }

    const int tid  = threadIdx.x;
    const int warp = tid >> 5, lane = tid & 31;
    const int wm = (warp & 3) * 32;
    const int wn = (warp >> 2) * 64;
    const int m0 = blockIdx.x * 128, n0 = blockIdx.y * 128;
    const int nk = K >> 5;

    const int lr = tid >> 1;
    const int lu = (tid & 1) * 16;
    const __nv_bfloat16* gAhi = Ahi + (long)(m0 + lr) * K + lu;
    const __nv_bfloat16* gAlo = Alo + (long)(m0 + lr) * K + lu;
    const __nv_bfloat16* gBhi = Bhi + (long)(n0 + lr) * K + lu;
    const __nv_bfloat16* gBlo = Blo + (long)(n0 + lr) * K + lu;
    const uint32_t sbase = smem_u32(hs);
    const uint32_t so = (lr * WROW + lu) * 2;

    const int a_r = (lane & 15);
    const int a_c = (lane >> 4) << 3;
    const int b_r = ((lane >> 4) << 3) + (lane & 7);
    const int b_c = ((lane >> 3) & 1) << 3;

    float acc[16][4];
#pragma unroll
    for (int i = 0; i < 16; i++)
#pragma unroll
        for (int j = 0; j < 4; j++) acc[i][j] = 0.f;

#define ISSUE(kb, buf)                                                       \
    do {                                                                     \
        const int _ko = (kb) * 32;                                           \
        uint32_t _d = sbase + (uint32_t)(buf) * (HS_PERBUF * 2) + so;        \
        CP_ASYNC16(_d,                  gAhi + _ko);                         \
        CP_ASYNC16(_d + 16,             gAhi + _ko + 8);                     \
        CP_ASYNC16(_d + HS_ARR * 2,     gAlo + _ko);                         \
        CP_ASYNC16(_d + HS_ARR * 2 + 16, gAlo + _ko + 8);                    \
        CP_ASYNC16(_d + HS_ARR * 4,     gBhi + _ko);                         \
        CP_ASYNC16(_d + HS_ARR * 4 + 16, gBhi + _ko + 8);                    \
        CP_ASYNC16(_d + HS_ARR * 6,     gBlo + _ko);                         \
        CP_ASYNC16(_d + HS_ARR * 6 + 16, gBlo + _ko + 8);                    \
    } while (0)

    ISSUE(0, 0);
    CP_COMMIT();

    for (int kb = 0; kb < nk; kb++) {
        if (kb + 1 < nk) {
            ISSUE(kb + 1, (kb + 1) & 1);
            CP_COMMIT();
            CP_WAIT1();
        } else {
            CP_WAIT0();
        }
        __syncthreads();

        const uint32_t bufb = sbase + (uint32_t)(kb & 1) * (HS_PERBUF * 2);
#pragma unroll
        for (int kh = 0; kh < 32; kh += 16) {
            uint32_t ah[2][4], al[2][4];
#pragma unroll
            for (int mt = 0; mt < 2; mt++) {
                uint32_t off = bufb + ((wm + mt * 16 + a_r) * WROW + kh + a_c) * 2;
                ldsm_x4(ah[mt][0], ah[mt][1], ah[mt][2], ah[mt][3], off);
                ldsm_x4(al[mt][0], al[mt][1], al[mt][2], al[mt][3],
                        off + HS_ARR * 2);
            }
            uint32_t bh[8][2], bl[8][2];
#pragma unroll
            for (int p = 0; p < 4; p++) {
                uint32_t off = bufb + HS_ARR * 4 +
                               ((wn + p * 16 + b_r) * WROW + kh + b_c) * 2;
                ldsm_x4(bh[p * 2][0], bh[p * 2][1], bh[p * 2 + 1][0],
                        bh[p * 2 + 1][1], off);
                ldsm_x4(bl[p * 2][0], bl[p * 2][1], bl[p * 2 + 1][0],
                        bl[p * 2 + 1][1], off + HS_ARR * 2);
            }
#pragma unroll
            for (int mt = 0; mt < 2; mt++)
#pragma unroll
                for (int nt = 0; nt < 8; nt++) {
                    float* c = acc[mt * 8 + nt];
                    mma_bf16(c, ah[mt], bh[nt]);
                    mma_bf16(c, ah[mt], bl[nt]);
                    mma_bf16(c, al[mt], bh[nt]);
                }
        }
        __syncthreads();
    }
#undef ISSUE

    const int g  = lane >> 2;
    const int c2 = (lane & 3) * 2;
#pragma unroll
    for (int nt = 0; nt < 8; nt++) {
        const int col = n0 + wn + nt * 8 + c2;
        float b0 = 0.f, b1 = 0.f;
        if (bias) { b0 = bias[col]; b1 = bias[col + 1]; }
#pragma unroll
        for (int mt = 0; mt < 2; mt++) {
            const float* c = acc[mt * 8 + nt];
            const int r0 = m0 + wm + mt * 16 + g;
            long o0 = (long)r0 * ldc + col;
            long o1 = (long)(r0 + 8) * ldc + col;
            float2 v0 = make_float2(c[0] * scale + b0, c[1] * scale + b1);
            float2 v1 = make_float2(c[2] * scale + b0, c[3] * scale + b1);
            if (outsplit) {
                __nv_bfloat16 h00 = __float2bfloat16(v0.x);
                __nv_bfloat16 h01 = __float2bfloat16(v0.y);
                __nv_bfloat16 h10 = __float2bfloat16(v1.x);
                __nv_bfloat16 h11 = __float2bfloat16(v1.y);
                __nv_bfloat162 ph0 = {h00, h01}, ph1 = {h10, h11};
                __nv_bfloat162 pl0 = {__float2bfloat16(v0.x - __bfloat162float(h00)),
                                      __float2bfloat16(v0.y - __bfloat162float(h01))};
                __nv_bfloat162 pl1 = {__float2bfloat16(v1.x - __bfloat162float(h10)),
                                      __float2bfloat16(v1.y - __bfloat162float(h11))};
                *(__nv_bfloat162*)(Chi + o0) = ph0;
                *(__nv_bfloat162*)(Chi + o1) = ph1;
                *(__nv_bfloat162*)(Clo + o0) = pl0;
                *(__nv_bfloat162*)(Clo + o1) = pl1;
            } else {
                if (accum) {
                    float2 e0 = *(const float2*)(C + o0);
                    float2 e1 = *(const float2*)(C + o1);
                    v0.x += e0.x; v0.y += e0.y; v1.x += e1.x; v1.y += e1.y;
                }
                *(float2*)(C + o0) = v0;
                *(float2*)(C + o1) = v1;
            }
        }
    }
}

// ---------------------------------------------------------------------------
// Masked softmax per (b, q) row; emits bf16 hi/lo out-of-place
// ---------------------------------------------------------------------------
__global__ void softmax_kernel(const float* __restrict__ sc,
                               const int* __restrict__ len,
                               __nv_bfloat16* __restrict__ shi,
                               __nv_bfloat16* __restrict__ slo) {
    const int q = blockIdx.x, b = blockIdx.y;
    const float* row = sc + ((long)b * SS + q) * SS;
    __nv_bfloat16* ohi = shi + ((long)b * SS + q) * SS;
    __nv_bfloat16* olo = slo + ((long)b * SS + q) * SS;
    const int L = len[b];
    const int t = threadIdx.x;
    __shared__ float red[256];
    const __nv_bfloat16 z = __float2bfloat16(0.f);
    if (q >= L) {
        for (int i = t; i < SS; i += 256) { ohi[i] = z; olo[i] = z; }
        return;
    }
    float m = -3.402823466e38f;
    for (int i = t; i < L; i += 256) m = fmaxf(m, row[i]);
    red[t] = m; __syncthreads();
    for (int s = 128; s > 0; s >>= 1) {
        if (t < s) red[t] = fmaxf(red[t], red[t + s]);
        __syncthreads();
    }
    m = red[0]; __syncthreads();
    float sum = 0.f;
    for (int i = t; i < L; i += 256) sum += expf(row[i] - m);
    red[t] = sum; __syncthreads();
    for (int s = 128; s > 0; s >>= 1) {
        if (t < s) red[t] += red[t + s];
        __syncthreads();
    }
    float inv = 1.f / red[0];
    for (int i = t; i < SS; i += 256) {
        float v = (i < L) ? expf(row[i] - m) * inv : 0.f;
        __nv_bfloat16 hi = __float2bfloat16(v);
        ohi[i] = hi;
        olo[i] = __float2bfloat16(v - __bfloat162float(hi));
    }
}

// ---------------------------------------------------------------------------
// Build layer input + fused bf16 hi/lo split
// ---------------------------------------------------------------------------
__global__ void build_lay(const float* __restrict__ hf, const float* __restrict__ hb,
                          const int* __restrict__ len, float* __restrict__ lay,
                          __nv_bfloat16* __restrict__ shi,
                          __nv_bfloat16* __restrict__ slo) {
    int r = blockIdx.x;
    int b = r >> 9, tt = r & 511;
    int active = tt < len[b];
    int t = threadIdx.x;
    for (int i = t; i < D2; i += 256) {
        float v = 0.f;
        if (active) v = (i < HH) ? hf[(long)r * HH + i] : hb[(long)r * HH + i - HH];
        lay[(long)r * D2 + i] = v;
        __nv_bfloat16 hi = __float2bfloat16(v);
        shi[(long)r * D2 + i] = hi;
        slo[(long)r * D2 + i] = __float2bfloat16(v - __bfloat162float(hi));
    }
}

// ---------------------------------------------------------------------------
// refined = LN(encoded + tanh(pre)) masked; emits bf16 hi/lo only
// ---------------------------------------------------------------------------
__global__ void refine_ln(const float* __restrict__ enc, const float* __restrict__ pre,
                          const float* __restrict__ g, const float* __restrict__ bta,
                          const int* __restrict__ len,
                          __nv_bfloat16* __restrict__ shi,
                          __nv_bfloat16* __restrict__ slo) {
    int r = blockIdx.x;
    int b = r >> 9, tt = r & 511;
    int t = threadIdx.x;
    __shared__ float r1[256], r2[256];
    float v[4];
    float s = 0.f, s2 = 0.f;
#pragma unroll
    for (int i = 0; i < 4; i++) {
        int idx = t + i * 256;
        float xx = enc[(long)r * D2 + idx] + tanhf(pre[(long)r * D2 + idx]);
        v[i] = xx; s += xx; s2 += xx * xx;
    }
    r1[t] = s; r2[t] = s2; __syncthreads();
    for (int st = 128; st > 0; st >>= 1) {
        if (t < st) { r1[t] += r1[t + st]; r2[t] += r2[t + st]; }
        __syncthreads();
    }
    float mean = r1[0] * (1.f / 1024.f);
    float var = r2[0] * (1.f / 1024.f) - mean * mean;
    float inv = rsqrtf(var + 1e-5f);
    int active = tt < len[b];
#pragma unroll
    for (int i = 0; i < 4; i++) {
        int idx = t + i * 256;
        float o = (v[i] - mean) * inv * g[idx] + bta[idx];
        o = active ? o : 0.f;
        __nv_bfloat16 hi = __float2bfloat16(o);
        shi[(long)r * D2 + idx] = hi;
        slo[(long)r * D2 + idx] = __float2bfloat16(o - __bfloat162float(hi));
    }
}

// ---------------------------------------------------------------------------
// head = LN(gelu_exact(hpre)) -> emit bf16 hi/lo split
// ---------------------------------------------------------------------------
__global__ void head_ln(const float* __restrict__ hpre, const float* __restrict__ g,
                        const float* __restrict__ bta,
                        __nv_bfloat16* __restrict__ hhi,
                        __nv_bfloat16* __restrict__ hlo) {
    int r = blockIdx.x;
    int t = threadIdx.x;
    __shared__ float r1[256], r2[256];
    float v[2];
    float s = 0.f, s2 = 0.f;
#pragma unroll
    for (int i = 0; i < 2; i++) {
        int idx = t + i * 256;
        float xx = hpre[(long)r * HH + idx];
        float ge = 0.5f * xx * (1.f + erff(xx * 0.70710678118654752f));
        v[i] = ge; s += ge; s2 += ge * ge;
    }
    r1[t] = s; r2[t] = s2; __syncthreads();
    for (int st = 128; st > 0; st >>= 1) {
        if (t < st) { r1[t] += r1[t + st]; r2[t] += r2[t + st]; }
        __syncthreads();
    }
    float mean = r1[0] * (1.f / 512.f);
    float var = r2[0] * (1.f / 512.f) - mean * mean;
    float inv = rsqrtf(var + 1e-5f);
#pragma unroll
    for (int i = 0; i < 2; i++) {
        int idx = t + i * 256;
        float o = (v[i] - mean) * inv * g[idx] + bta[idx];
        __nv_bfloat16 hi = __float2bfloat16(o);
        float lo = o - __bfloat162float(hi);
        hhi[(long)r * HH + idx] = hi;
        hlo[(long)r * HH + idx] = __float2bfloat16(lo);
    }
}

// ---------------------------------------------------------------------------
// Reset grid barrier counters
// ---------------------------------------------------------------------------
__global__ void reset_bar() { g_barcnt2[0] = 0u; g_barcnt2[1] = 0u; }

// ---------------------------------------------------------------------------
// Persistent BiLSTM scan — tensor-core GEMV (unchanged; xp row stride X4)
// ---------------------------------------------------------------------------
#define LROW 520
#define LS_W   (16 * LROW)
#define LSTM_SMEM (4 * LS_W * 2 + 1024 * 4 + 128 * 4 + 32 * 4)

__global__ __launch_bounds__(256, 2) void lstm_scan(
    const float* __restrict__ xc,
    const float* __restrict__ Wrf, const float* __restrict__ Wrb,
    const float* __restrict__ h0f, const float* __restrict__ c0f,
    const float* __restrict__ h0b, const float* __restrict__ c0b,
    float* __restrict__ houtf, float* __restrict__ houtb,
    float* __restrict__ hcur, const int* __restrict__ len)
{
    extern __shared__ char smraw[];
    __nv_bfloat16* sWhi = (__nv_bfloat16*)smraw;
    __nv_bfloat16* sWlo = sWhi + LS_W;
    __nv_bfloat16* sAhi = sWlo + LS_W;
    __nv_bfloat16* sAlo = sAhi + LS_W;
    float* part  = (float*)(sAlo + LS_W);
    float* gates = part + 1024;
    float* cst   = gates + 128;

    const int tid  = threadIdx.x;
    const int warp = tid >> 5, lane = tid & 31;
    const int dir = blockIdx.x >> 7;
    const int kb  = blockIdx.x & 127;
    const int j0  = kb * 4;
    const float* Wr = dir ? Wrb : Wrf;
    const float* xp = xc + dir * G4;
    const float* h0 = dir ? h0b : h0f;
    const float* c0 = dir ? c0b : c0f;
    float* hout  = dir ? houtb : houtf;
    float* hbase = hcur + dir * (2 * BB * HH);
    volatile unsigned* barp = &g_barcnt2[dir];

    {
        int col = tid & 15;
        int gcol = (col >> 2) * 512 + j0 + (col & 3);
        for (int k = tid >> 4; k < 512; k += 16) {
            float v = Wr[(long)k * G4 + gcol];
            __nv_bfloat16 hi = __float2bfloat16(v);
            sWhi[col * LROW + k] = hi;
            sWlo[col * LROW + k] = __float2bfloat16(v - __bfloat162float(hi));
        }
    }
    for (int f = tid; f < 8 * LROW; f += 256) {
        sAhi[8 * LROW + f] = __float2bfloat16(0.f);
        sAlo[8 * LROW + f] = __float2bfloat16(0.f);
    }
    if (tid < 32) {
        int u = tid >> 3, b = tid & 7;
        cst[u * 8 + b] = c0[j0 + u];
        __stcg(&hbase[(j0 + u) * 8 + b], h0[j0 + u]);
    }

    const uint32_t sAhiB = smem_u32(sAhi), sAloB = smem_u32(sAlo);
    const uint32_t sWhiB = smem_u32(sWhi), sWloB = smem_u32(sWlo);
    const int kbase = warp * 64;
    const uint32_t aoff = ((lane & 15) * LROW + kbase + ((lane >> 4) << 3)) * 2;
    const uint32_t boff = ((((lane >> 4) << 3) + (lane & 7)) * LROW + kbase +
                          (((lane >> 3) & 1) << 3)) * 2;

    unsigned phase = 1;
#define GRIDBAR()                                                         \
    do {                                                                  \
        __syncthreads();                                                  \
        if (tid == 0) {                                                   \
            __threadfence();                                              \
            atomicAdd((unsigned*)barp, 1u);                               \
            unsigned tgt = 128u * phase;                                  \
            while (*barp < tgt) {}                                        \
        }                                                                 \
        __syncthreads();                                                  \
        phase++;                                                          \
    } while (0)

    GRIDBAR();

    for (int s = 0; s < SS; s++) {
        const float* hrd = hbase + (s & 1) * (BB * HH);
        float* hwr = hbase + ((s + 1) & 1) * (BB * HH);
        const int t_real = dir ? (SS - 1 - s) : s;

        float xpv = 0.f;
        if (tid < 128) {
            int col = tid >> 3, b = tid & 7;
            xpv = __ldg(&xp[((long)(b * SS + t_real)) * X4 +
                            (col >> 2) * 512 + j0 + (col & 3)]);
        }
        float hpv = 0.f;
        if (tid < 32)
            hpv = __ldcg(&hrd[(j0 + (tid >> 3)) * 8 + (tid & 7)]);

        {
            int b = tid & 7, kp = tid >> 3;
#pragma unroll
            for (int i = 0; i < 8; i++) {
                int k = (kp + 32 * i) * 2;
                float v0 = __ldcg(hrd + k * 8 + b);
                float v1 = __ldcg(hrd + (k + 1) * 8 + b);
                __nv_bfloat16 hh0 = __float2bfloat16(v0);
                __nv_bfloat16 hh1 = __float2bfloat16(v1);
                __nv_bfloat162 ph = {hh0, hh1};
                __nv_bfloat162 pl = {__float2bfloat16(v0 - __bfloat162float(hh0)),
                                     __float2bfloat16(v1 - __bfloat162float(hh1))};
                *(__nv_bfloat162*)&sAhi[b * LROW + k] = ph;
                *(__nv_bfloat162*)&sAlo[b * LROW + k] = pl;
            }
        }
        __syncthreads();

        float acA[2][4], acB[2][4];
#pragma unroll
        for (int nt = 0; nt < 2; nt++)
#pragma unroll
            for (int j = 0; j < 4; j++) { acA[nt][j] = 0.f; acB[nt][j] = 0.f; }
#pragma unroll
        for (int kk = 0; kk < 4; kk++) {
            uint32_t ah[4], al[4], bh4[4], bl4[4];
            ldsm_x4(ah[0], ah[1], ah[2], ah[3], sAhiB + aoff + kk * 32);
            ldsm_x4(al[0], al[1], al[2], al[3], sAloB + aoff + kk * 32);
            ldsm_x4(bh4[0], bh4[1], bh4[2], bh4[3], sWhiB + boff + kk * 32);
            ldsm_x4(bl4[0], bl4[1], bl4[2], bl4[3], sWloB + boff + kk * 32);
            float (*ac)[4] = (kk & 1) ? acB : acA;
            uint32_t bh0[2] = {bh4[0], bh4[1]}, bh1[2] = {bh4[2], bh4[3]};
            uint32_t bl0[2] = {bl4[0], bl4[1]}, bl1[2] = {bl4[2], bl4[3]};
            mma_bf16(ac[0], ah, bh0);
            mma_bf16(ac[0], ah, bl0);
            mma_bf16(ac[0], al, bh0);
            mma_bf16(ac[1], ah, bh1);
            mma_bf16(ac[1], ah, bl1);
            mma_bf16(ac[1], al, bh1);
        }
        {
            int g = lane >> 2, c2 = (lane & 3) * 2;
#pragma unroll
            for (int nt = 0; nt < 2; nt++) {
                part[warp * 128 + (nt * 8 + c2) * 8 + g]     = acA[nt][0] + acB[nt][0];
                part[warp * 128 + (nt * 8 + c2 + 1) * 8 + g] = acA[nt][1] + acB[nt][1];
            }
        }
        __syncthreads();

        if (tid < 128) {
            float ssum = xpv;
#pragma unroll
            for (int w = 0; w < 8; w++) ssum += part[w * 128 + tid];
            gates[tid] = ssum;
        }
        __syncthreads();

        if (tid < 32) {
            int u = tid >> 3, b = tid & 7;
            float ig = gates[(u) * 8 + b];
            float fg = gates[(4 + u) * 8 + b];
            float og = gates[(8 + u) * 8 + b];
            float gg = gates[(12 + u) * 8 + b];
            float cp = cst[u * 8 + b];
            float cn = sigm(fg) * cp + sigm(ig) * tanhf(gg);
            float hn = sigm(og) * tanhf(cn);
            int active = t_real < len[b];
            float h = active ? hn : hpv;
            float c = active ? cn : cp;
            cst[u * 8 + b] = c;
            __stcg(&hwr[(j0 + u) * 8 + b], h);
            hout[((long)(b * SS + t_real)) * HH + j0 + u] = h;
        }
        GRIDBAR();
    }
#undef GRIDBAR
}

// ---------------------------------------------------------------------------
// Host driver
// ---------------------------------------------------------------------------
extern "C" void kernel_launch(void* const* d_in, const int* in_sizes, int n_in,
                              void* d_out, int out_size) {
    const int*   x    = (const int*)  d_in[0];
    const float* emb  = (const float*)d_in[1];
    const float* Wf0  = (const float*)d_in[2];
    const float* bf0  = (const float*)d_in[3];
    const float* Wb0  = (const float*)d_in[4];
    const float* bb0  = (const float*)d_in[5];
    const float* Wf1  = (const float*)d_in[6];
    const float* bf1  = (const float*)d_in[7];
    const float* Wb1  = (const float*)d_in[8];
    const float* bb1  = (const float*)d_in[9];
    const float* h0f  = (const float*)d_in[10];
    const float* c0f  = (const float*)d_in[11];
    const float* h0b  = (const float*)d_in[12];
    const float* c0b  = (const float*)d_in[13];
    const float* Wq   = (const float*)d_in[14];
    const float* bq   = (const float*)d_in[15];
    const float* Wao  = (const float*)d_in[16];
    const float* bao  = (const float*)d_in[17];
    const float* ln1g = (const float*)d_in[18];
    const float* ln1b = (const float*)d_in[19];
    const float* Wh   = (const float*)d_in[20];
    const float* bh   = (const float*)d_in[21];
    const float* ln2g = (const float*)d_in[22];
    const float* ln2b = (const float*)d_in[23];
    const float* Wp   = (const float*)d_in[24];
    const float* ob   = (const float*)d_in[25];
    float* out = (float*)d_out;

    float *xc, *hf, *hb, *lay, *scores, *pre, *hpre, *hcur, *bcat;
    __nv_bfloat16 *ahi, *alo, *bhi, *blo, *ehi, *elo, *hhi, *hlo, *wpthi, *wptlo;
    int* len;
    cudaGetSymbolAddress((void**)&xc,     g_xc);
    cudaGetSymbolAddress((void**)&hf,     g_hf);
    cudaGetSymbolAddress((void**)&hb,     g_hb);
    cudaGetSymbolAddress((void**)&lay,    g_lay);
    cudaGetSymbolAddress((void**)&scores, g_scores);
    cudaGetSymbolAddress((void**)&pre,    g_pre);
    cudaGetSymbolAddress((void**)&hpre,   g_hpre);
    cudaGetSymbolAddress((void**)&hcur,   g_hcur);
    cudaGetSymbolAddress((void**)&bcat,   g_bcat);
    cudaGetSymbolAddress((void**)&len,    g_len);
    cudaGetSymbolAddress((void**)&ahi,    g_ahi);
    cudaGetSymbolAddress((void**)&alo,    g_alo);
    cudaGetSymbolAddress((void**)&bhi,    g_bhi);
    cudaGetSymbolAddress((void**)&blo,    g_blo);
    cudaGetSymbolAddress((void**)&ehi,    g_ehi);
    cudaGetSymbolAddress((void**)&elo,    g_elo);
    cudaGetSymbolAddress((void**)&hhi,    g_hhi);
    cudaGetSymbolAddress((void**)&hlo,    g_hlo);
    cudaGetSymbolAddress((void**)&wpthi,  g_wpthi);
    cudaGetSymbolAddress((void**)&wptlo,  g_wptlo);

    cudaFuncSetAttribute(lstm_scan, cudaFuncAttributeMaxDynamicSharedMemorySize,
                         LSTM_SMEM);
    cudaFuncSetAttribute(hgemm, cudaFuncAttributeMaxDynamicSharedMemorySize,
                         HGEMM_SMEM);

    len_kernel<<<BB, 512>>>(x, len);
    embed_kernel<<<NROW, 128>>>(x, emb, ahi, alo);   // fused embed+split
    wt_split<<<dim3(VV / 32, HH / 32), dim3(32, 8)>>>(Wp, VV, HH, wpthi, wptlo, 0, 0);

    // ---- layer 0: combined projection (Wf0 | Wb0), N = 4096 ----
    wt_split<<<dim3(G4 / 32, EE / 32), dim3(32, 8)>>>(Wf0, G4, EE, bhi, blo, 0, 0);
    wt_split<<<dim3(G4 / 32, EE / 32), dim3(32, 8)>>>(Wb0, G4, EE,
        bhi + (long)G4 * EE, blo + (long)G4 * EE, 0, 0);
    cudaMemcpyAsync(bcat, bf0, G4 * sizeof(float), cudaMemcpyDeviceToDevice);
    cudaMemcpyAsync(bcat + G4, bb0, G4 * sizeof(float), cudaMemcpyDeviceToDevice);
    hgemm<<<dim3(NROW / 128, X4 / 128), 256, HGEMM_SMEM>>>(
        ahi, alo, bhi, blo, bcat, xc, X4, EE, X4, 1.f, 0, 0, 0, 0,
        nullptr, nullptr, 0);

    reset_bar<<<1, 1>>>();
    lstm_scan<<<256, 256, LSTM_SMEM>>>(xc,
                                       Wf0 + (long)EE * G4, Wb0 + (long)EE * G4,
                                       h0f, c0f, h0b, c0b, hf, hb, hcur, len);
    build_lay<<<NROW, 256>>>(hf, hb, len, lay, ahi, alo);

    // ---- layer 1: combined projection (Wf1 | Wb1); A = (ahi, alo) fused ----
    wt_split<<<dim3(G4 / 32, D2 / 32), dim3(32, 8)>>>(Wf1, G4, D2, bhi, blo, 0, 0);
    wt_split<<<dim3(G4 / 32, D2 / 32), dim3(32, 8)>>>(Wb1, G4, D2,
        bhi + (long)G4 * D2, blo + (long)G4 * D2, 0, 0);
    cudaMemcpyAsync(bcat, bf1, G4 * sizeof(float), cudaMemcpyDeviceToDevice);
    cudaMemcpyAsync(bcat + G4, bb1, G4 * sizeof(float), cudaMemcpyDeviceToDevice);
    hgemm<<<dim3(NROW / 128, X4 / 128), 256, HGEMM_SMEM>>>(
        ahi, alo, bhi, blo, bcat, xc, X4, D2, X4, 1.f, 0, 0, 0, 0,
        nullptr, nullptr, 0);

    reset_bar<<<1, 1>>>();
    lstm_scan<<<256, 256, LSTM_SMEM>>>(xc,
                                       Wf1 + (long)D2 * G4, Wb1 + (long)D2 * G4,
                                       h0f + HH, c0f + HH, h0b + HH, c0b + HH,
                                       hf, hb, hcur, len);
    build_lay<<<NROW, 256>>>(hf, hb, len, lay, ehi, elo);  // lay = encoded + split

    // ---- attention ----
    // query = enc @ Wq + bq  (outsplit -> ahi/alo)
    wt_split<<<dim3(D2 / 32, D2 / 32), dim3(32, 8)>>>(Wq, D2, D2, bhi, blo, 0, 0);
    hgemm<<<dim3(NROW / 128, D2 / 128), 256, HGEMM_SMEM>>>(
        ehi, elo, bhi, blo, bq, nullptr, D2, D2, D2, 1.f, 0, 0, 0, 0,
        ahi, alo, 1);
    // scores = scale * query @ enc^T  (fp32 out)
    hgemm<<<dim3(SS / 128, SS / 128, BB), 256, HGEMM_SMEM>>>(
        ahi, alo, ehi, elo, nullptr, scores, SS, D2, SS, 0.03125f, 0,
        (long)SS * D2, (long)SS * D2, (long)SS * SS, nullptr, nullptr, 0);
    // softmax -> bf16 hi/lo (attn in ahi/alo)
    softmax_kernel<<<dim3(SS, BB), 256>>>(scores, len, ahi, alo);
    // pre = enc @ Wao[:D2] + bao  (must run before ehi/elo is reused)
    wt_split<<<dim3(D2 / 32, D2 / 32), dim3(32, 8)>>>(Wao, D2, D2, bhi, blo, 0, 0);
    hgemm<<<dim3(NROW / 128, D2 / 128), 256, HGEMM_SMEM>>>(
        ehi, elo, bhi, blo, bao, pre, D2, D2, D2, 1.f, 0, 0, 0, 0,
        nullptr, nullptr, 0);
    // ctx = attn @ enc  (B = per-batch enc^T; outsplit -> ehi/elo)
    wt_split<<<dim3(D2 / 32, SS / 32, BB), dim3(32, 8)>>>(
        lay, D2, SS, bhi, blo, (long)SS * D2, (long)D2 * SS);
    hgemm<<<dim3(SS / 128, D2 / 128, BB), 256, HGEMM_SMEM>>>(
        ahi, alo, bhi, blo, nullptr, nullptr, D2, SS, D2, 1.f, 0,
        (long)SS * SS, (long)D2 * SS, (long)SS * D2, ehi, elo, 1);
    // pre += ctx @ Wao[D2:]
    wt_split<<<dim3(D2 / 32, D2 / 32), dim3(32, 8)>>>(Wao + (long)D2 * D2, D2, D2,
                                                      bhi, blo, 0, 0);
    hgemm<<<dim3(NROW / 128, D2 / 128), 256, HGEMM_SMEM>>>(
        ehi, elo, bhi, blo, nullptr, pre, D2, D2, D2, 1.f, 1, 0, 0, 0,
        nullptr, nullptr, 0);
    refine_ln<<<NROW, 256>>>(lay, pre, ln1g, ln1b, len, ahi, alo);

    // ---- head ----
    wt_split<<<dim3(HH / 32, D2 / 32), dim3(32, 8)>>>(Wh, HH, D2, bhi, blo, 0, 0);
    hgemm<<<dim3(NROW / 128, HH / 128), 256, HGEMM_SMEM>>>(
        ahi, alo, bhi, blo, bh, hpre, HH, D2, HH, 1.f, 0, 0, 0, 0,
        nullptr, nullptr, 0);
    head_ln<<<NROW, 256>>>(hpre, ln2g, ln2b, hhi, hlo);

    // ---- vocab projection ----
    hgemm<<<dim3(NROW / 128, VV / 128), 256, HGEMM_SMEM>>>(
        hhi, hlo, wpthi, wptlo, ob, out, VV, HH, VV, 1.f, 0, 0, 0, 0,
        nullptr, nullptr, 0);
}